// round 13
// baseline (speedup 1.0000x reference)
#include <cuda_runtime.h>
#include <cuda_bf16.h>
#include <math.h>
#include <stdint.h>

#define HID   1024
#define GATES 4096
#define BB    8
#define TT    256
#define MM    2048
#define VOC   50257
#define NPART ((VOC + 127) / 128)      // 393 decoder column tiles

typedef unsigned long long u64;

// ---------------- scratch ----------------
__device__ float g_xproj[(size_t)GATES * MM];       // TRANSPOSED: [gate][m]
__device__ float g_hbuf[2][BB * HID];
__device__ float g_c[BB * HID];
__device__ float g_lse[MM];
__device__ float2 g_lsepart[(size_t)MM * NPART];
__device__ int   g_bar_flags[128 * 32];             // one flag per CTA, 128B apart

// bf16 split operands
__device__ __nv_bfloat16 g_ebh[(size_t)VOC * HID];
__device__ __nv_bfloat16 g_ebl[(size_t)VOC * HID];
__device__ __nv_bfloat16 g_wh [(size_t)GATES * HID];
__device__ __nv_bfloat16 g_wl [(size_t)GATES * HID];
__device__ __nv_bfloat16 g_rwh[(size_t)GATES * HID];
__device__ __nv_bfloat16 g_rwl[(size_t)GATES * HID];
__device__ __nv_bfloat16 g_xh [(size_t)MM * HID];
__device__ __nv_bfloat16 g_xl [(size_t)MM * HID];
__device__ __nv_bfloat16 g_hh2[(size_t)MM * HID];
__device__ __nv_bfloat16 g_hl2[(size_t)MM * HID];

// ---------------- helpers ----------------
__device__ __forceinline__ void cpasync16(uint32_t dst, const void* src) {
    asm volatile("cp.async.cg.shared.global [%0], [%1], 16;\n" :: "r"(dst), "l"(src));
}
#define CP_COMMIT() asm volatile("cp.async.commit_group;\n")

__device__ __forceinline__ float fexp(float x) {
    float y = fmaxf(x * 1.4426950408889634f, -120.f);
    float n = rintf(y);
    float f = y - n;
    float p = 0.0013333558f;
    p = fmaf(p, f, 0.0096181291f);
    p = fmaf(p, f, 0.0555041087f);
    p = fmaf(p, f, 0.2402265069f);
    p = fmaf(p, f, 0.6931471806f);
    p = fmaf(p, f, 1.0f);
    return p * __int_as_float(((int)n + 127) << 23);
}

__device__ __forceinline__ void mma16816(float* d, const uint32_t* a, const uint32_t* b) {
    asm volatile(
        "mma.sync.aligned.m16n8k16.row.col.f32.bf16.bf16.f32 "
        "{%0,%1,%2,%3}, {%4,%5,%6,%7}, {%8,%9}, {%0,%1,%2,%3};"
        : "+f"(d[0]), "+f"(d[1]), "+f"(d[2]), "+f"(d[3])
        : "r"(a[0]), "r"(a[1]), "r"(a[2]), "r"(a[3]), "r"(b[0]), "r"(b[1]));
}

__device__ __forceinline__ void ldm_x4(uint32_t* r, uint32_t addr) {
    asm volatile("ldmatrix.sync.aligned.m8n8.x4.shared.b16 {%0,%1,%2,%3}, [%4];"
        : "=r"(r[0]), "=r"(r[1]), "=r"(r[2]), "=r"(r[3]) : "r"(addr));
}

__device__ __forceinline__ uint32_t pkbf(float a, float b) {
    return ((uint32_t)__bfloat16_as_ushort(__float2bfloat16(b)) << 16)
         | __bfloat16_as_ushort(__float2bfloat16(a));
}
__device__ __forceinline__ void split8(float4 a, float4 b, uint4& ph, uint4& pl) {
    float h0 = __bfloat162float(__float2bfloat16(a.x));
    float h1 = __bfloat162float(__float2bfloat16(a.y));
    float h2 = __bfloat162float(__float2bfloat16(a.z));
    float h3 = __bfloat162float(__float2bfloat16(a.w));
    float h4 = __bfloat162float(__float2bfloat16(b.x));
    float h5 = __bfloat162float(__float2bfloat16(b.y));
    float h6 = __bfloat162float(__float2bfloat16(b.z));
    float h7 = __bfloat162float(__float2bfloat16(b.w));
    ph.x = pkbf(a.x, a.y); ph.y = pkbf(a.z, a.w);
    ph.z = pkbf(b.x, b.y); ph.w = pkbf(b.z, b.w);
    pl.x = pkbf(a.x - h0, a.y - h1); pl.y = pkbf(a.z - h2, a.w - h3);
    pl.z = pkbf(b.x - h4, b.y - h5); pl.w = pkbf(b.z - h6, b.w - h7);
}

// ---------------- small kernels ----------------
__global__ void zero_state_kernel() {
    int i = blockIdx.x * blockDim.x + threadIdx.x;
    if (i < BB * HID) { g_hbuf[0][i] = 0.f; g_c[i] = 0.f; }
    if (i < 128 * 32) g_bar_flags[i] = 0;
}

__global__ void gather_kernel(const int* __restrict__ x, const float* __restrict__ embW,
                              __nv_bfloat16* __restrict__ xh, __nv_bfloat16* __restrict__ xl) {
    int m = blockIdx.x;
    int t = m >> 3, b = m & 7;
    int tok = x[b * TT + t];
    const float4* src = (const float4*)(embW + (size_t)tok * HID);
    int i = threadIdx.x;
    float4 a = src[2 * i], c = src[2 * i + 1];
    uint4 ph, pl;
    split8(a, c, ph, pl);
    ((uint4*)(xh + (size_t)m * HID))[i] = ph;
    ((uint4*)(xl + (size_t)m * HID))[i] = pl;
}

__global__ void split_kernel(const float* __restrict__ s, __nv_bfloat16* __restrict__ h,
                             __nv_bfloat16* __restrict__ l, long n8) {
    long i = blockIdx.x * (long)blockDim.x + threadIdx.x;
    long st = (long)gridDim.x * blockDim.x;
    const float4* s4 = (const float4*)s;
    for (; i < n8; i += st) {
        float4 a = s4[2 * i], b = s4[2 * i + 1];
        uint4 ph, pl;
        split8(a, b, ph, pl);
        ((uint4*)h)[i] = ph;
        ((uint4*)l)[i] = pl;
    }
}

// ---------------- mma.sync split-bf16 NT GEMM (ldmatrix fragment loads) ----------------
#define BKP 40
#define BUF_B (128 * BKP * 2)
#define STAGE_B (4 * BUF_B)
#define MMSMEM (2 * STAGE_B)

__device__ __forceinline__ void stage_chunk_mma(
    char* smem, int stage, int tid, int kc,
    const __nv_bfloat16* Ah, const __nv_bfloat16* Al,
    const __nv_bfloat16* Bh, const __nv_bfloat16* Bl,
    int m0, int n0, int Nrows, int K)
{
    uint32_t sb = (uint32_t)__cvta_generic_to_shared(smem) + (uint32_t)stage * STAGE_B;
    #pragma unroll
    for (int i = 0; i < 8; i++) {
        int u = tid + 256 * i;
        int buf = u >> 9;
        int o = u & 511;
        int row = o >> 2;
        int col = (o & 3) * 8;
        const __nv_bfloat16* src;
        if (buf < 2) {
            src = ((buf == 0) ? Ah : Al) + (size_t)(m0 + row) * K + kc + col;
        } else {
            int n = n0 + row; if (n >= Nrows) n = Nrows - 1;
            src = ((buf == 2) ? Bh : Bl) + (size_t)n * K + kc + col;
        }
        cpasync16(sb + (uint32_t)(buf * BUF_B + (row * BKP + col) * 2), src);
    }
}

__global__ void __launch_bounds__(256)
mm_bf16_kernel(const __nv_bfloat16* __restrict__ Ah, const __nv_bfloat16* __restrict__ Al,
               const __nv_bfloat16* __restrict__ Bh, const __nv_bfloat16* __restrict__ Bl,
               const float* __restrict__ bias1, const float* __restrict__ bias2,
               float* __restrict__ C, int Nrows, int ldc, int K,
               float2* __restrict__ lse_part)
{
    extern __shared__ char smem[];
    int tid = threadIdx.x;
    int wid = tid >> 5, lane = tid & 31;
    int m0 = blockIdx.x * 128;
    int n0 = blockIdx.y * 128;
    int m0w = (wid >> 2) * 64;
    int n0w = (wid & 3) * 32;
    const int NC = K / 32;
    uint32_t smem_u32 = (uint32_t)__cvta_generic_to_shared(smem);

    float acc[4][4][4];
    #pragma unroll
    for (int mf = 0; mf < 4; mf++)
        #pragma unroll
        for (int nf = 0; nf < 4; nf++)
            #pragma unroll
            for (int e = 0; e < 4; e++) acc[mf][nf][e] = 0.f;

    stage_chunk_mma(smem, 0, tid, 0, Ah, Al, Bh, Bl, m0, n0, Nrows, K);
    CP_COMMIT();
    stage_chunk_mma(smem, 1, tid, 32, Ah, Al, Bh, Bl, m0, n0, Nrows, K);
    CP_COMMIT();

    int ar = lane >> 2;
    int ac = (lane & 3) * 2;
    // ldmatrix per-lane address components
    uint32_t aoff = (uint32_t)(((m0w + (lane & 15)) * BKP + (lane >> 4) * 8) * 2);
    uint32_t boff = (uint32_t)(((n0w + (lane & 15)) * BKP + (lane >> 4) * 8) * 2);

    for (int c = 0; c < NC; c++) {
        if (c < NC - 1) asm volatile("cp.async.wait_group 1;" ::: "memory");
        else            asm volatile("cp.async.wait_group 0;" ::: "memory");
        __syncthreads();

        uint32_t stb = smem_u32 + (uint32_t)(c & 1) * STAGE_B;
        uint32_t aAh = stb + aoff;                 // Ah buffer
        uint32_t aAl = stb + BUF_B + aoff;         // Al
        uint32_t aBh = stb + 2u * BUF_B + boff;    // Bh
        uint32_t aBl = stb + 3u * BUF_B + boff;    // Bl

        #pragma unroll
        for (int ks = 0; ks < 32; ks += 16) {
            uint32_t ko = (uint32_t)(ks * 2);
            uint32_t fAh[4][4], fAl[4][4], fBh[4][2], fBl[4][2];
            #pragma unroll
            for (int mf = 0; mf < 4; mf++) {
                ldm_x4(fAh[mf], aAh + ko + (uint32_t)(mf * 16 * BKP * 2));
                ldm_x4(fAl[mf], aAl + ko + (uint32_t)(mf * 16 * BKP * 2));
            }
            #pragma unroll
            for (int bb = 0; bb < 2; bb++) {
                uint32_t q[4];
                ldm_x4(q, aBh + ko + (uint32_t)(bb * 16 * BKP * 2));
                fBh[2 * bb][0] = q[0]; fBh[2 * bb + 1][0] = q[1];
                fBh[2 * bb][1] = q[2]; fBh[2 * bb + 1][1] = q[3];
                ldm_x4(q, aBl + ko + (uint32_t)(bb * 16 * BKP * 2));
                fBl[2 * bb][0] = q[0]; fBl[2 * bb + 1][0] = q[1];
                fBl[2 * bb][1] = q[2]; fBl[2 * bb + 1][1] = q[3];
            }
            #pragma unroll
            for (int mf = 0; mf < 4; mf++)
                #pragma unroll
                for (int nf = 0; nf < 4; nf++) {
                    mma16816(acc[mf][nf], fAh[mf], fBh[nf]);
                    mma16816(acc[mf][nf], fAh[mf], fBl[nf]);
                    mma16816(acc[mf][nf], fAl[mf], fBh[nf]);
                }
        }
        __syncthreads();
        if (c + 2 < NC) {
            stage_chunk_mma(smem, c & 1, tid, (c + 2) * 32, Ah, Al, Bh, Bl, m0, n0, Nrows, K);
            CP_COMMIT();
        }
    }

    // epilogue: scalar stores + optional online (max, sumexp) per row
    float rmax[4][2], rsum[4][2];
    #pragma unroll
    for (int mf = 0; mf < 4; mf++) { rmax[mf][0] = rmax[mf][1] = -1e30f; rsum[mf][0] = rsum[mf][1] = 0.f; }

    #pragma unroll
    for (int mf = 0; mf < 4; mf++) {
        int row0 = m0 + m0w + mf * 16 + ar;
        float* r0p = C + (size_t)row0 * ldc;
        float* r1p = C + (size_t)(row0 + 8) * ldc;
        #pragma unroll
        for (int nf = 0; nf < 4; nf++) {
            int col = n0 + n0w + nf * 8 + ac;
            #pragma unroll
            for (int e = 0; e < 2; e++) {
                int cc = col + e;
                if (cc < Nrows) {
                    float bv = 0.f;
                    if (bias1) bv += bias1[cc];
                    if (bias2) bv += bias2[cc];
                    float v0 = acc[mf][nf][e] + bv;
                    float v1 = acc[mf][nf][2 + e] + bv;
                    r0p[cc] = v0;
                    r1p[cc] = v1;
                    if (lse_part) {
                        if (v0 > rmax[mf][0]) { rsum[mf][0] = rsum[mf][0] * fexp(rmax[mf][0] - v0) + 1.f; rmax[mf][0] = v0; }
                        else                  { rsum[mf][0] += fexp(v0 - rmax[mf][0]); }
                        if (v1 > rmax[mf][1]) { rsum[mf][1] = rsum[mf][1] * fexp(rmax[mf][1] - v1) + 1.f; rmax[mf][1] = v1; }
                        else                  { rsum[mf][1] += fexp(v1 - rmax[mf][1]); }
                    }
                }
            }
        }
    }

    if (lse_part) {
        #pragma unroll
        for (int mf = 0; mf < 4; mf++)
            #pragma unroll
            for (int h = 0; h < 2; h++) {
                float m = rmax[mf][h], s = rsum[mf][h];
                #pragma unroll
                for (int off = 1; off <= 2; off <<= 1) {
                    float m2 = __shfl_xor_sync(0xffffffffu, m, off);
                    float s2 = __shfl_xor_sync(0xffffffffu, s, off);
                    float mm = fmaxf(m, m2);
                    s = s * fexp(m - mm) + s2 * fexp(m2 - mm);
                    m = mm;
                }
                rmax[mf][h] = m; rsum[mf][h] = s;
            }
        __syncthreads();
        float2* sp = (float2*)smem;
        if ((lane & 3) == 0) {
            #pragma unroll
            for (int mf = 0; mf < 4; mf++)
                #pragma unroll
                for (int h = 0; h < 2; h++) {
                    int rc = m0w + mf * 16 + ar + h * 8;
                    sp[rc * 4 + (wid & 3)] = make_float2(rmax[mf][h], rsum[mf][h]);
                }
        }
        __syncthreads();
        if (tid < 128) {
            float m = -1e30f, s = 0.f;
            #pragma unroll
            for (int w = 0; w < 4; w++) {
                float2 p = sp[tid * 4 + w];
                float mm = fmaxf(m, p.x);
                s = s * fexp(m - mm) + p.y * fexp(p.x - mm);
                m = mm;
            }
            lse_part[(size_t)(m0 + tid) * NPART + blockIdx.y] = make_float2(m, s);
        }
    }
}

// ---------------- persistent LSTM ----------------
#define WPAD 1032
#define LP_SWH 0
#define LP_SWL 66048
#define LP_SHH 132096
#define LP_SHL 148608
#define LP_RED 165120
#define LP_GATES 173312
#define LP_BIAS 174336
#define LP_SMEM 174464

__global__ void __launch_bounds__(256)
lstm_persistent_kernel(const __nv_bfloat16* __restrict__ rwh,
                       const __nv_bfloat16* __restrict__ rwl,
                       const float* __restrict__ b_ih,
                       const float* __restrict__ b_hh)
{
    extern __shared__ char smraw[];
    __nv_bfloat16* swh = (__nv_bfloat16*)(smraw + LP_SWH);
    __nv_bfloat16* swl = (__nv_bfloat16*)(smraw + LP_SWL);
    __nv_bfloat16* shh = (__nv_bfloat16*)(smraw + LP_SHH);
    __nv_bfloat16* shl = (__nv_bfloat16*)(smraw + LP_SHL);
    float* red      = (float*)(smraw + LP_RED);
    float* sm_gates = (float*)(smraw + LP_GATES);
    float* sm_bias  = (float*)(smraw + LP_BIAS);

    int tid = threadIdx.x;
    int jb = blockIdx.x * 8;

    {
        uint32_t sb = (uint32_t)__cvta_generic_to_shared(smraw);
        #pragma unroll
        for (int i = 0; i < 32; i++) {
            int u = tid + 256 * i;
            int buf = u >> 12;
            int o = u & 4095;
            int row = o >> 7;
            int ch = o & 127;
            int g = row >> 3, jl = row & 7;
            const __nv_bfloat16* src = (buf ? rwl : rwh)
                + (size_t)(g * HID + jb + jl) * HID + ch * 8;
            cpasync16(sb + (uint32_t)(buf * LP_SWL + row * (WPAD * 2) + ch * 16), src);
        }
        CP_COMMIT();
        if (tid < 32) {
            int g = tid >> 3, jl = tid & 7;
            sm_bias[tid] = b_ih[g * HID + jb + jl] + b_hh[g * HID + jb + jl];
        }
        asm volatile("cp.async.wait_group 0;\n" ::: "memory");
        __syncthreads();
    }

    int wid = tid >> 5, lane = tid & 31;
    int ar = lane >> 2;
    int ac = (lane & 3) * 2;
    int ejl = tid >> 3, eb = tid & 7;
    float c_reg = 0.f;

    const float* xpp;
    {
        int prow = tid >> 3, pb = tid & 7;
        int pg = prow >> 3, pjl = prow & 7;
        xpp = g_xproj + (size_t)(pg * HID + jb + pjl) * MM + pb;
    }

    for (int t = 0; t < TT; t++) {
        const float* hprev = g_hbuf[t & 1];
        float* hnext = g_hbuf[(t + 1) & 1];

        float xp_pre = __ldcg(xpp + t * BB);

        {
            const float4* hp4 = (const float4*)hprev;
            #pragma unroll
            for (int i = 0; i < 8; i++) {
                int f4 = tid + 256 * i;
                float4 v = __ldcg(hp4 + f4);
                int batch = f4 >> 8;
                int k = (f4 & 255) * 4;
                int off = batch * WPAD + k;
                float h0 = __bfloat162float(__float2bfloat16(v.x));
                float h1 = __bfloat162float(__float2bfloat16(v.y));
                float h2 = __bfloat162float(__float2bfloat16(v.z));
                float h3 = __bfloat162float(__float2bfloat16(v.w));
                uint2 ph, pl;
                ph.x = pkbf(v.x, v.y);
                ph.y = pkbf(v.z, v.w);
                pl.x = pkbf(v.x - h0, v.y - h1);
                pl.y = pkbf(v.z - h2, v.w - h3);
                *(uint2*)(shh + off) = ph;
                *(uint2*)(shl + off) = pl;
            }
        }
        __syncthreads();

        float acc[2][4];
        #pragma unroll
        for (int mt = 0; mt < 2; mt++)
            #pragma unroll
            for (int e = 0; e < 4; e++) acc[mt][e] = 0.f;

        #pragma unroll
        for (int ks8 = 0; ks8 < 8; ks8++) {
            int kk = wid * 128 + ks8 * 16;
            uint32_t bh[2], bl[2];
            bh[0] = *(const uint32_t*)(shh + ar * WPAD + kk + ac);
            bh[1] = *(const uint32_t*)(shh + ar * WPAD + kk + ac + 8);
            bl[0] = *(const uint32_t*)(shl + ar * WPAD + kk + ac);
            bl[1] = *(const uint32_t*)(shl + ar * WPAD + kk + ac + 8);
            #pragma unroll
            for (int mt = 0; mt < 2; mt++) {
                int r = mt * 16 + ar;
                uint32_t ah[4], al[4];
                ah[0] = *(const uint32_t*)(swh + r * WPAD + kk + ac);
                ah[1] = *(const uint32_t*)(swh + (r + 8) * WPAD + kk + ac);
                ah[2] = *(const uint32_t*)(swh + r * WPAD + kk + ac + 8);
                ah[3] = *(const uint32_t*)(swh + (r + 8) * WPAD + kk + ac + 8);
                al[0] = *(const uint32_t*)(swl + r * WPAD + kk + ac);
                al[1] = *(const uint32_t*)(swl + (r + 8) * WPAD + kk + ac);
                al[2] = *(const uint32_t*)(swl + r * WPAD + kk + ac + 8);
                al[3] = *(const uint32_t*)(swl + (r + 8) * WPAD + kk + ac + 8);
                mma16816(acc[mt], ah, bh);
                mma16816(acc[mt], ah, bl);
                mma16816(acc[mt], al, bh);
            }
        }

        #pragma unroll
        for (int mt = 0; mt < 2; mt++)
            #pragma unroll
            for (int e = 0; e < 4; e++) {
                int row = mt * 16 + ar + ((e & 2) ? 8 : 0);
                int b = ac + (e & 1);
                red[row * 64 + b * 8 + wid] = acc[mt][e];
            }
        __syncthreads();

        {
            float4 p0 = *(float4*)(red + tid * 8);
            float4 p1 = *(float4*)(red + tid * 8 + 4);
            sm_gates[tid] = ((p0.x + p0.y) + (p0.z + p0.w))
                          + ((p1.x + p1.y) + (p1.z + p1.w))
                          + xp_pre + sm_bias[tid >> 3];
        }
        __syncthreads();

        if (tid < 64) {
            int j = jb + ejl;
            float gi = sm_gates[(0 * 8 + ejl) * 8 + eb];
            float gf = sm_gates[(1 * 8 + ejl) * 8 + eb];
            float gg = sm_gates[(2 * 8 + ejl) * 8 + eb];
            float go = sm_gates[(3 * 8 + ejl) * 8 + eb];
            gi = 1.f / (1.f + expf(-gi));
            gf = 1.f / (1.f + expf(-gf));
            gg = tanhf(gg);
            go = 1.f / (1.f + expf(-go));
            c_reg = gf * c_reg + gi * gg;
            float h = go * tanhf(c_reg);
            hnext[eb * HID + j] = h;
            size_t di = ((size_t)eb * TT + t) * HID + j;
            float hh = __bfloat162float(__float2bfloat16(h));
            g_hh2[di] = __float2bfloat16(h);
            g_hl2[di] = __float2bfloat16(h - hh);
            if (t == TT - 1) g_c[eb * HID + j] = c_reg;
        }

        // flat all-poll grid barrier
        __syncthreads();
        __threadfence();
        if (tid == 0)
            *(volatile int*)&g_bar_flags[blockIdx.x * 32] = t + 1;
        if (wid == 0) {
            int idx = lane * 4;
            for (;;) {
                int ok = 1;
                #pragma unroll
                for (int q = 0; q < 4; q++)
                    ok &= (*(volatile int*)&g_bar_flags[(idx + q) * 32] >= t + 1);
                if (__all_sync(0xffffffffu, ok)) break;
            }
        }
        __syncthreads();
    }
}

// ---------------- LSE partial reduce + subtract ----------------
__global__ void __launch_bounds__(256)
lse_reduce_kernel(const float2* __restrict__ part)
{
    int row = blockIdx.x * 8 + (threadIdx.x >> 5);
    int lane = threadIdx.x & 31;
    float m = -1e30f, s = 0.f;
    for (int i = lane; i < NPART; i += 32) {
        float2 p = part[(size_t)row * NPART + i];
        float mm = fmaxf(m, p.x);
        s = s * fexp(m - mm) + p.y * fexp(p.x - mm);
        m = mm;
    }
    #pragma unroll
    for (int off = 16; off; off >>= 1) {
        float m2 = __shfl_xor_sync(0xffffffffu, m, off);
        float s2 = __shfl_xor_sync(0xffffffffu, s, off);
        float mm = fmaxf(m, m2);
        s = s * fexp(m - mm) + s2 * fexp(m2 - mm);
        m = mm;
    }
    if (lane == 0) g_lse[row] = m + logf(s);
}

__global__ void __launch_bounds__(256)
sub_lse_kernel(float* __restrict__ out)
{
    int row = blockIdx.x;
    float l = g_lse[row];
    float* p = out + (size_t)row * VOC;
    for (int i = threadIdx.x; i < VOC; i += 256) p[i] -= l;
}

__global__ void write_hidden_kernel(float* __restrict__ out)
{
    int i = blockIdx.x * blockDim.x + threadIdx.x;
    size_t base = (size_t)MM * VOC;
    if (i < BB * HID)               out[base + i] = g_hbuf[0][i];
    else if (i < 2 * BB * HID)      out[base + i] = g_c[i - BB * HID];
}

// ---------------- launcher ----------------
extern "C" void kernel_launch(void* const* d_in, const int* in_sizes, int n_in,
                              void* d_out, int out_size)
{
    const int*   x     = (const int*)  d_in[0];
    const float* emb_W = (const float*)d_in[1];
    const float* w_ih  = (const float*)d_in[2];
    const float* w_hh  = (const float*)d_in[3];
    const float* b_ih  = (const float*)d_in[4];
    const float* b_hh  = (const float*)d_in[5];
    const float* dec_b = (const float*)d_in[6];
    float* out = (float*)d_out;

    float* xproj_p; cudaGetSymbolAddress((void**)&xproj_p, g_xproj);
    float2* lsepart_p; cudaGetSymbolAddress((void**)&lsepart_p, g_lsepart);
    __nv_bfloat16 *ebh, *ebl, *wh, *wl, *rwh, *rwl, *xh, *xl, *hh2, *hl2;
    cudaGetSymbolAddress((void**)&ebh, g_ebh);
    cudaGetSymbolAddress((void**)&ebl, g_ebl);
    cudaGetSymbolAddress((void**)&wh,  g_wh);
    cudaGetSymbolAddress((void**)&wl,  g_wl);
    cudaGetSymbolAddress((void**)&rwh, g_rwh);
    cudaGetSymbolAddress((void**)&rwl, g_rwl);
    cudaGetSymbolAddress((void**)&xh,  g_xh);
    cudaGetSymbolAddress((void**)&xl,  g_xl);
    cudaGetSymbolAddress((void**)&hh2, g_hh2);
    cudaGetSymbolAddress((void**)&hl2, g_hl2);

    cudaFuncSetAttribute(lstm_persistent_kernel,
                         cudaFuncAttributeMaxDynamicSharedMemorySize, LP_SMEM);
    cudaFuncSetAttribute(mm_bf16_kernel,
                         cudaFuncAttributeMaxDynamicSharedMemorySize, MMSMEM);

    zero_state_kernel<<<(BB * HID + 255) / 256, 256>>>();

    gather_kernel<<<MM, 128>>>(x, emb_W, xh, xl);

    split_kernel<<<4096, 256>>>(emb_W, ebh, ebl, (long)VOC * HID / 8);
    split_kernel<<<512,  256>>>(w_ih,  wh,  wl,  (long)GATES * HID / 8);
    split_kernel<<<512,  256>>>(w_hh,  rwh, rwl, (long)GATES * HID / 8);

    // x_proj TRANSPOSED: C[gate][m] = w_ih @ emb^T (bias folded into LSTM)
    {
        dim3 grid(GATES / 128, MM / 128);
        mm_bf16_kernel<<<grid, 256, MMSMEM>>>(wh, wl, xh, xl,
                                              (const float*)0, (const float*)0,
                                              xproj_p, MM, MM, HID, (float2*)0);
    }

    lstm_persistent_kernel<<<HID / 8, 256, LP_SMEM>>>(rwh, rwl, b_ih, b_hh);

    // decoder: logits = h_all @ emb_W^T + dec_b, with fused LSE partials
    {
        dim3 grid(MM / 128, NPART);
        mm_bf16_kernel<<<grid, 256, MMSMEM>>>(hh2, hl2, ebh, ebl, dec_b,
                                              (const float*)0, out, VOC, VOC, HID,
                                              lsepart_p);
    }

    lse_reduce_kernel<<<MM / 8, 256>>>(lsepart_p);
    sub_lse_kernel<<<MM, 256>>>(out);

    if (out_size >= MM * VOC + 2 * BB * HID)
        write_hidden_kernel<<<(2 * BB * HID + 255) / 256, 256>>>(out);
}

// round 14
// speedup vs baseline: 1.4236x; 1.4236x over previous
#include <cuda_runtime.h>
#include <cuda_bf16.h>
#include <math.h>
#include <stdint.h>

#define HID   1024
#define GATES 4096
#define BB    8
#define TT    256
#define MM    2048
#define VOC   50257
#define NPART ((VOC + 127) / 128)      // 393 decoder column tiles

typedef unsigned long long u64;

// ---------------- scratch ----------------
__device__ float g_xproj[(size_t)GATES * MM];       // TRANSPOSED: [gate][m]
__device__ float g_hbuf[2][BB * HID];
__device__ float g_c[BB * HID];
__device__ float g_lse[MM];
__device__ float2 g_lsepart[(size_t)MM * NPART];
__device__ int   g_bar_flags[128 * 32];             // one flag per CTA, 128B apart

// bf16 split operands
__device__ __nv_bfloat16 g_ebh[(size_t)VOC * HID];
__device__ __nv_bfloat16 g_ebl[(size_t)VOC * HID];
__device__ __nv_bfloat16 g_wh [(size_t)GATES * HID];
__device__ __nv_bfloat16 g_wl [(size_t)GATES * HID];
__device__ __nv_bfloat16 g_rwh[(size_t)GATES * HID];
__device__ __nv_bfloat16 g_rwl[(size_t)GATES * HID];
__device__ __nv_bfloat16 g_xh [(size_t)MM * HID];
__device__ __nv_bfloat16 g_xl [(size_t)MM * HID];
__device__ __nv_bfloat16 g_hh2[(size_t)MM * HID];
__device__ __nv_bfloat16 g_hl2[(size_t)MM * HID];

// ---------------- helpers ----------------
__device__ __forceinline__ void cpasync16(uint32_t dst, const void* src) {
    asm volatile("cp.async.cg.shared.global [%0], [%1], 16;\n" :: "r"(dst), "l"(src));
}
#define CP_COMMIT() asm volatile("cp.async.commit_group;\n")

__device__ __forceinline__ float fexp(float x) {
    float y = fmaxf(x * 1.4426950408889634f, -120.f);
    float n = rintf(y);
    float f = y - n;
    float p = 0.0013333558f;
    p = fmaf(p, f, 0.0096181291f);
    p = fmaf(p, f, 0.0555041087f);
    p = fmaf(p, f, 0.2402265069f);
    p = fmaf(p, f, 0.6931471806f);
    p = fmaf(p, f, 1.0f);
    return p * __int_as_float(((int)n + 127) << 23);
}

__device__ __forceinline__ void mma16816(float* d, const uint32_t* a, const uint32_t* b) {
    asm volatile(
        "mma.sync.aligned.m16n8k16.row.col.f32.bf16.bf16.f32 "
        "{%0,%1,%2,%3}, {%4,%5,%6,%7}, {%8,%9}, {%0,%1,%2,%3};"
        : "+f"(d[0]), "+f"(d[1]), "+f"(d[2]), "+f"(d[3])
        : "r"(a[0]), "r"(a[1]), "r"(a[2]), "r"(a[3]), "r"(b[0]), "r"(b[1]));
}

__device__ __forceinline__ uint32_t pkbf(float a, float b) {
    return ((uint32_t)__bfloat16_as_ushort(__float2bfloat16(b)) << 16)
         | __bfloat16_as_ushort(__float2bfloat16(a));
}
__device__ __forceinline__ void split8(float4 a, float4 b, uint4& ph, uint4& pl) {
    float h0 = __bfloat162float(__float2bfloat16(a.x));
    float h1 = __bfloat162float(__float2bfloat16(a.y));
    float h2 = __bfloat162float(__float2bfloat16(a.z));
    float h3 = __bfloat162float(__float2bfloat16(a.w));
    float h4 = __bfloat162float(__float2bfloat16(b.x));
    float h5 = __bfloat162float(__float2bfloat16(b.y));
    float h6 = __bfloat162float(__float2bfloat16(b.z));
    float h7 = __bfloat162float(__float2bfloat16(b.w));
    ph.x = pkbf(a.x, a.y); ph.y = pkbf(a.z, a.w);
    ph.z = pkbf(b.x, b.y); ph.w = pkbf(b.z, b.w);
    pl.x = pkbf(a.x - h0, a.y - h1); pl.y = pkbf(a.z - h2, a.w - h3);
    pl.z = pkbf(b.x - h4, b.y - h5); pl.w = pkbf(b.z - h6, b.w - h7);
}

// ---------------- small kernels ----------------
__global__ void zero_state_kernel() {
    int i = blockIdx.x * blockDim.x + threadIdx.x;
    if (i < BB * HID) { g_hbuf[0][i] = 0.f; g_c[i] = 0.f; }
    if (i < 128 * 32) g_bar_flags[i] = 0;
}

__global__ void gather_kernel(const int* __restrict__ x, const float* __restrict__ embW,
                              __nv_bfloat16* __restrict__ xh, __nv_bfloat16* __restrict__ xl) {
    int m = blockIdx.x;
    int t = m >> 3, b = m & 7;
    int tok = x[b * TT + t];
    const float4* src = (const float4*)(embW + (size_t)tok * HID);
    int i = threadIdx.x;
    float4 a = src[2 * i], c = src[2 * i + 1];
    uint4 ph, pl;
    split8(a, c, ph, pl);
    ((uint4*)(xh + (size_t)m * HID))[i] = ph;
    ((uint4*)(xl + (size_t)m * HID))[i] = pl;
}

__global__ void split_kernel(const float* __restrict__ s, __nv_bfloat16* __restrict__ h,
                             __nv_bfloat16* __restrict__ l, long n8) {
    long i = blockIdx.x * (long)blockDim.x + threadIdx.x;
    long st = (long)gridDim.x * blockDim.x;
    const float4* s4 = (const float4*)s;
    for (; i < n8; i += st) {
        float4 a = s4[2 * i], b = s4[2 * i + 1];
        uint4 ph, pl;
        split8(a, b, ph, pl);
        ((uint4*)h)[i] = ph;
        ((uint4*)l)[i] = pl;
    }
}

// ---------------- mma.sync split-bf16 NT GEMM (scalar LDS fragments, KC=64) ----------------
#define BKP 72                          // padded bf16 row stride (64 data + 8 pad)
#define KC  64
#define BUF_B (128 * BKP * 2)           // 18432 bytes per operand buffer
#define STAGE_B (4 * BUF_B)             // 73728
#define MMSMEM (2 * STAGE_B)            // 147456

__device__ __forceinline__ void stage_chunk_mma(
    char* smem, int stage, int tid, int kc,
    const __nv_bfloat16* Ah, const __nv_bfloat16* Al,
    const __nv_bfloat16* Bh, const __nv_bfloat16* Bl,
    int m0, int n0, int Nrows, int K)
{
    uint32_t sb = (uint32_t)__cvta_generic_to_shared(smem) + (uint32_t)stage * STAGE_B;
    #pragma unroll
    for (int i = 0; i < 16; i++) {
        int u = tid + 256 * i;              // 0..4095 16B-units
        int buf = u >> 10;                  // 0:Ah 1:Al 2:Bh 3:Bl
        int o = u & 1023;
        int row = o >> 3;                   // 0..127
        int col = (o & 7) * 8;              // 0..56
        const __nv_bfloat16* src;
        if (buf < 2) {
            src = ((buf == 0) ? Ah : Al) + (size_t)(m0 + row) * K + kc + col;
        } else {
            int n = n0 + row; if (n >= Nrows) n = Nrows - 1;
            src = ((buf == 2) ? Bh : Bl) + (size_t)n * K + kc + col;
        }
        cpasync16(sb + (uint32_t)(buf * BUF_B + (row * BKP + col) * 2), src);
    }
}

__global__ void __launch_bounds__(256)
mm_bf16_kernel(const __nv_bfloat16* __restrict__ Ah, const __nv_bfloat16* __restrict__ Al,
               const __nv_bfloat16* __restrict__ Bh, const __nv_bfloat16* __restrict__ Bl,
               const float* __restrict__ bias1, const float* __restrict__ bias2,
               float* __restrict__ C, int Nrows, int ldc, int K,
               float2* __restrict__ lse_part)
{
    extern __shared__ char smem[];
    int tid = threadIdx.x;
    int wid = tid >> 5, lane = tid & 31;
    int m0 = blockIdx.x * 128;
    int n0 = blockIdx.y * 128;
    int m0w = (wid >> 2) * 64;
    int n0w = (wid & 3) * 32;
    const int NC = K / KC;                  // 16

    float acc[4][4][4];
    #pragma unroll
    for (int mf = 0; mf < 4; mf++)
        #pragma unroll
        for (int nf = 0; nf < 4; nf++)
            #pragma unroll
            for (int e = 0; e < 4; e++) acc[mf][nf][e] = 0.f;

    stage_chunk_mma(smem, 0, tid, 0, Ah, Al, Bh, Bl, m0, n0, Nrows, K);
    CP_COMMIT();
    stage_chunk_mma(smem, 1, tid, KC, Ah, Al, Bh, Bl, m0, n0, Nrows, K);
    CP_COMMIT();

    int ar = lane >> 2;
    int ac = (lane & 3) * 2;

    for (int c = 0; c < NC; c++) {
        if (c < NC - 1) asm volatile("cp.async.wait_group 1;" ::: "memory");
        else            asm volatile("cp.async.wait_group 0;" ::: "memory");
        __syncthreads();

        const __nv_bfloat16* st = (const __nv_bfloat16*)(smem + (c & 1) * STAGE_B);
        const __nv_bfloat16* pAh = st;
        const __nv_bfloat16* pAl = st + 128 * BKP;
        const __nv_bfloat16* pBh = st + 2 * 128 * BKP;
        const __nv_bfloat16* pBl = st + 3 * 128 * BKP;

        #pragma unroll
        for (int ks = 0; ks < KC; ks += 16) {
            uint32_t fAh[4][4], fAl[4][4], fBh[4][2], fBl[4][2];
            #pragma unroll
            for (int mf = 0; mf < 4; mf++) {
                int r = m0w + mf * 16 + ar;
                int cc = ks + ac;
                fAh[mf][0] = *(const uint32_t*)(pAh + r * BKP + cc);
                fAh[mf][1] = *(const uint32_t*)(pAh + (r + 8) * BKP + cc);
                fAh[mf][2] = *(const uint32_t*)(pAh + r * BKP + cc + 8);
                fAh[mf][3] = *(const uint32_t*)(pAh + (r + 8) * BKP + cc + 8);
                fAl[mf][0] = *(const uint32_t*)(pAl + r * BKP + cc);
                fAl[mf][1] = *(const uint32_t*)(pAl + (r + 8) * BKP + cc);
                fAl[mf][2] = *(const uint32_t*)(pAl + r * BKP + cc + 8);
                fAl[mf][3] = *(const uint32_t*)(pAl + (r + 8) * BKP + cc + 8);
            }
            #pragma unroll
            for (int nf = 0; nf < 4; nf++) {
                int n = n0w + nf * 8 + ar;
                int kk = ks + ac;
                fBh[nf][0] = *(const uint32_t*)(pBh + n * BKP + kk);
                fBh[nf][1] = *(const uint32_t*)(pBh + n * BKP + kk + 8);
                fBl[nf][0] = *(const uint32_t*)(pBl + n * BKP + kk);
                fBl[nf][1] = *(const uint32_t*)(pBl + n * BKP + kk + 8);
            }
            #pragma unroll
            for (int mf = 0; mf < 4; mf++)
                #pragma unroll
                for (int nf = 0; nf < 4; nf++) {
                    mma16816(acc[mf][nf], fAh[mf], fBh[nf]);
                    mma16816(acc[mf][nf], fAh[mf], fBl[nf]);
                    mma16816(acc[mf][nf], fAl[mf], fBh[nf]);
                }
        }
        __syncthreads();
        if (c + 2 < NC) {
            stage_chunk_mma(smem, c & 1, tid, (c + 2) * KC, Ah, Al, Bh, Bl, m0, n0, Nrows, K);
            CP_COMMIT();
        }
    }

    // epilogue: scalar stores + optional online (max, sumexp) per row
    float rmax[4][2], rsum[4][2];
    #pragma unroll
    for (int mf = 0; mf < 4; mf++) { rmax[mf][0] = rmax[mf][1] = -1e30f; rsum[mf][0] = rsum[mf][1] = 0.f; }

    #pragma unroll
    for (int mf = 0; mf < 4; mf++) {
        int row0 = m0 + m0w + mf * 16 + ar;
        float* r0p = C + (size_t)row0 * ldc;
        float* r1p = C + (size_t)(row0 + 8) * ldc;
        #pragma unroll
        for (int nf = 0; nf < 4; nf++) {
            int col = n0 + n0w + nf * 8 + ac;
            #pragma unroll
            for (int e = 0; e < 2; e++) {
                int cc = col + e;
                if (cc < Nrows) {
                    float bv = 0.f;
                    if (bias1) bv += bias1[cc];
                    if (bias2) bv += bias2[cc];
                    float v0 = acc[mf][nf][e] + bv;
                    float v1 = acc[mf][nf][2 + e] + bv;
                    r0p[cc] = v0;
                    r1p[cc] = v1;
                    if (lse_part) {
                        if (v0 > rmax[mf][0]) { rsum[mf][0] = rsum[mf][0] * fexp(rmax[mf][0] - v0) + 1.f; rmax[mf][0] = v0; }
                        else                  { rsum[mf][0] += fexp(v0 - rmax[mf][0]); }
                        if (v1 > rmax[mf][1]) { rsum[mf][1] = rsum[mf][1] * fexp(rmax[mf][1] - v1) + 1.f; rmax[mf][1] = v1; }
                        else                  { rsum[mf][1] += fexp(v1 - rmax[mf][1]); }
                    }
                }
            }
        }
    }

    if (lse_part) {
        #pragma unroll
        for (int mf = 0; mf < 4; mf++)
            #pragma unroll
            for (int h = 0; h < 2; h++) {
                float m = rmax[mf][h], s = rsum[mf][h];
                #pragma unroll
                for (int off = 1; off <= 2; off <<= 1) {
                    float m2 = __shfl_xor_sync(0xffffffffu, m, off);
                    float s2 = __shfl_xor_sync(0xffffffffu, s, off);
                    float mm = fmaxf(m, m2);
                    s = s * fexp(m - mm) + s2 * fexp(m2 - mm);
                    m = mm;
                }
                rmax[mf][h] = m; rsum[mf][h] = s;
            }
        __syncthreads();
        float2* sp = (float2*)smem;
        if ((lane & 3) == 0) {
            #pragma unroll
            for (int mf = 0; mf < 4; mf++)
                #pragma unroll
                for (int h = 0; h < 2; h++) {
                    int rc = m0w + mf * 16 + ar + h * 8;
                    sp[rc * 4 + (wid & 3)] = make_float2(rmax[mf][h], rsum[mf][h]);
                }
        }
        __syncthreads();
        if (tid < 128) {
            float m = -1e30f, s = 0.f;
            #pragma unroll
            for (int w = 0; w < 4; w++) {
                float2 p = sp[tid * 4 + w];
                float mm = fmaxf(m, p.x);
                s = s * fexp(m - mm) + p.y * fexp(p.x - mm);
                m = mm;
            }
            lse_part[(size_t)(m0 + tid) * NPART + blockIdx.y] = make_float2(m, s);
        }
    }
}

// ---------------- persistent LSTM ----------------
#define WPAD 1032
#define LP_SWH 0
#define LP_SWL 66048
#define LP_SHH 132096
#define LP_SHL 148608
#define LP_RED 165120
#define LP_GATES 173312
#define LP_BIAS 174336
#define LP_SMEM 174464

__global__ void __launch_bounds__(256)
lstm_persistent_kernel(const __nv_bfloat16* __restrict__ rwh,
                       const __nv_bfloat16* __restrict__ rwl,
                       const float* __restrict__ b_ih,
                       const float* __restrict__ b_hh)
{
    extern __shared__ char smraw[];
    __nv_bfloat16* swh = (__nv_bfloat16*)(smraw + LP_SWH);
    __nv_bfloat16* swl = (__nv_bfloat16*)(smraw + LP_SWL);
    __nv_bfloat16* shh = (__nv_bfloat16*)(smraw + LP_SHH);
    __nv_bfloat16* shl = (__nv_bfloat16*)(smraw + LP_SHL);
    float* red      = (float*)(smraw + LP_RED);
    float* sm_gates = (float*)(smraw + LP_GATES);
    float* sm_bias  = (float*)(smraw + LP_BIAS);

    int tid = threadIdx.x;
    int jb = blockIdx.x * 8;

    {
        uint32_t sb = (uint32_t)__cvta_generic_to_shared(smraw);
        #pragma unroll
        for (int i = 0; i < 32; i++) {
            int u = tid + 256 * i;
            int buf = u >> 12;
            int o = u & 4095;
            int row = o >> 7;
            int ch = o & 127;
            int g = row >> 3, jl = row & 7;
            const __nv_bfloat16* src = (buf ? rwl : rwh)
                + (size_t)(g * HID + jb + jl) * HID + ch * 8;
            cpasync16(sb + (uint32_t)(buf * LP_SWL + row * (WPAD * 2) + ch * 16), src);
        }
        CP_COMMIT();
        if (tid < 32) {
            int g = tid >> 3, jl = tid & 7;
            sm_bias[tid] = b_ih[g * HID + jb + jl] + b_hh[g * HID + jb + jl];
        }
        asm volatile("cp.async.wait_group 0;\n" ::: "memory");
        __syncthreads();
    }

    int wid = tid >> 5, lane = tid & 31;
    int ar = lane >> 2;
    int ac = (lane & 3) * 2;
    int ejl = tid >> 3, eb = tid & 7;
    float c_reg = 0.f;

    const float* xpp;
    {
        int prow = tid >> 3, pb = tid & 7;
        int pg = prow >> 3, pjl = prow & 7;
        xpp = g_xproj + (size_t)(pg * HID + jb + pjl) * MM + pb;
    }

    for (int t = 0; t < TT; t++) {
        const float* hprev = g_hbuf[t & 1];
        float* hnext = g_hbuf[(t + 1) & 1];

        float xp_pre = __ldcg(xpp + t * BB);

        {
            const float4* hp4 = (const float4*)hprev;
            #pragma unroll
            for (int i = 0; i < 8; i++) {
                int f4 = tid + 256 * i;
                float4 v = __ldcg(hp4 + f4);
                int batch = f4 >> 8;
                int k = (f4 & 255) * 4;
                int off = batch * WPAD + k;
                float h0 = __bfloat162float(__float2bfloat16(v.x));
                float h1 = __bfloat162float(__float2bfloat16(v.y));
                float h2 = __bfloat162float(__float2bfloat16(v.z));
                float h3 = __bfloat162float(__float2bfloat16(v.w));
                uint2 ph, pl;
                ph.x = pkbf(v.x, v.y);
                ph.y = pkbf(v.z, v.w);
                pl.x = pkbf(v.x - h0, v.y - h1);
                pl.y = pkbf(v.z - h2, v.w - h3);
                *(uint2*)(shh + off) = ph;
                *(uint2*)(shl + off) = pl;
            }
        }
        __syncthreads();

        float acc[2][4];
        #pragma unroll
        for (int mt = 0; mt < 2; mt++)
            #pragma unroll
            for (int e = 0; e < 4; e++) acc[mt][e] = 0.f;

        #pragma unroll
        for (int ks8 = 0; ks8 < 8; ks8++) {
            int kk = wid * 128 + ks8 * 16;
            uint32_t bh[2], bl[2];
            bh[0] = *(const uint32_t*)(shh + ar * WPAD + kk + ac);
            bh[1] = *(const uint32_t*)(shh + ar * WPAD + kk + ac + 8);
            bl[0] = *(const uint32_t*)(shl + ar * WPAD + kk + ac);
            bl[1] = *(const uint32_t*)(shl + ar * WPAD + kk + ac + 8);
            #pragma unroll
            for (int mt = 0; mt < 2; mt++) {
                int r = mt * 16 + ar;
                uint32_t ah[4], al[4];
                ah[0] = *(const uint32_t*)(swh + r * WPAD + kk + ac);
                ah[1] = *(const uint32_t*)(swh + (r + 8) * WPAD + kk + ac);
                ah[2] = *(const uint32_t*)(swh + r * WPAD + kk + ac + 8);
                ah[3] = *(const uint32_t*)(swh + (r + 8) * WPAD + kk + ac + 8);
                al[0] = *(const uint32_t*)(swl + r * WPAD + kk + ac);
                al[1] = *(const uint32_t*)(swl + (r + 8) * WPAD + kk + ac);
                al[2] = *(const uint32_t*)(swl + r * WPAD + kk + ac + 8);
                al[3] = *(const uint32_t*)(swl + (r + 8) * WPAD + kk + ac + 8);
                mma16816(acc[mt], ah, bh);
                mma16816(acc[mt], ah, bl);
                mma16816(acc[mt], al, bh);
            }
        }

        #pragma unroll
        for (int mt = 0; mt < 2; mt++)
            #pragma unroll
            for (int e = 0; e < 4; e++) {
                int row = mt * 16 + ar + ((e & 2) ? 8 : 0);
                int b = ac + (e & 1);
                red[row * 64 + b * 8 + wid] = acc[mt][e];
            }
        __syncthreads();

        {
            float4 p0 = *(float4*)(red + tid * 8);
            float4 p1 = *(float4*)(red + tid * 8 + 4);
            sm_gates[tid] = ((p0.x + p0.y) + (p0.z + p0.w))
                          + ((p1.x + p1.y) + (p1.z + p1.w))
                          + xp_pre + sm_bias[tid >> 3];
        }
        __syncthreads();

        if (tid < 64) {
            int j = jb + ejl;
            float gi = sm_gates[(0 * 8 + ejl) * 8 + eb];
            float gf = sm_gates[(1 * 8 + ejl) * 8 + eb];
            float gg = sm_gates[(2 * 8 + ejl) * 8 + eb];
            float go = sm_gates[(3 * 8 + ejl) * 8 + eb];
            gi = 1.f / (1.f + expf(-gi));
            gf = 1.f / (1.f + expf(-gf));
            gg = tanhf(gg);
            go = 1.f / (1.f + expf(-go));
            c_reg = gf * c_reg + gi * gg;
            float h = go * tanhf(c_reg);
            hnext[eb * HID + j] = h;
            size_t di = ((size_t)eb * TT + t) * HID + j;
            float hh = __bfloat162float(__float2bfloat16(h));
            g_hh2[di] = __float2bfloat16(h);
            g_hl2[di] = __float2bfloat16(h - hh);
            if (t == TT - 1) g_c[eb * HID + j] = c_reg;
        }

        // flat all-poll grid barrier
        __syncthreads();
        __threadfence();
        if (tid == 0)
            *(volatile int*)&g_bar_flags[blockIdx.x * 32] = t + 1;
        if (wid == 0) {
            int idx = lane * 4;
            for (;;) {
                int ok = 1;
                #pragma unroll
                for (int q = 0; q < 4; q++)
                    ok &= (*(volatile int*)&g_bar_flags[(idx + q) * 32] >= t + 1);
                if (__all_sync(0xffffffffu, ok)) break;
            }
        }
        __syncthreads();
    }
}

// ---------------- LSE partial reduce + subtract ----------------
__global__ void __launch_bounds__(256)
lse_reduce_kernel(const float2* __restrict__ part)
{
    int row = blockIdx.x * 8 + (threadIdx.x >> 5);
    int lane = threadIdx.x & 31;
    float m = -1e30f, s = 0.f;
    for (int i = lane; i < NPART; i += 32) {
        float2 p = part[(size_t)row * NPART + i];
        float mm = fmaxf(m, p.x);
        s = s * fexp(m - mm) + p.y * fexp(p.x - mm);
        m = mm;
    }
    #pragma unroll
    for (int off = 16; off; off >>= 1) {
        float m2 = __shfl_xor_sync(0xffffffffu, m, off);
        float s2 = __shfl_xor_sync(0xffffffffu, s, off);
        float mm = fmaxf(m, m2);
        s = s * fexp(m - mm) + s2 * fexp(m2 - mm);
        m = mm;
    }
    if (lane == 0) g_lse[row] = m + logf(s);
}

__global__ void __launch_bounds__(256)
sub_lse_kernel(float* __restrict__ out)
{
    int row = blockIdx.x;
    float l = g_lse[row];
    float* p = out + (size_t)row * VOC;
    for (int i = threadIdx.x; i < VOC; i += 256) p[i] -= l;
}

__global__ void write_hidden_kernel(float* __restrict__ out)
{
    int i = blockIdx.x * blockDim.x + threadIdx.x;
    size_t base = (size_t)MM * VOC;
    if (i < BB * HID)               out[base + i] = g_hbuf[0][i];
    else if (i < 2 * BB * HID)      out[base + i] = g_c[i - BB * HID];
}

// ---------------- launcher ----------------
extern "C" void kernel_launch(void* const* d_in, const int* in_sizes, int n_in,
                              void* d_out, int out_size)
{
    const int*   x     = (const int*)  d_in[0];
    const float* emb_W = (const float*)d_in[1];
    const float* w_ih  = (const float*)d_in[2];
    const float* w_hh  = (const float*)d_in[3];
    const float* b_ih  = (const float*)d_in[4];
    const float* b_hh  = (const float*)d_in[5];
    const float* dec_b = (const float*)d_in[6];
    float* out = (float*)d_out;

    float* xproj_p; cudaGetSymbolAddress((void**)&xproj_p, g_xproj);
    float2* lsepart_p; cudaGetSymbolAddress((void**)&lsepart_p, g_lsepart);
    __nv_bfloat16 *ebh, *ebl, *wh, *wl, *rwh, *rwl, *xh, *xl, *hh2, *hl2;
    cudaGetSymbolAddress((void**)&ebh, g_ebh);
    cudaGetSymbolAddress((void**)&ebl, g_ebl);
    cudaGetSymbolAddress((void**)&wh,  g_wh);
    cudaGetSymbolAddress((void**)&wl,  g_wl);
    cudaGetSymbolAddress((void**)&rwh, g_rwh);
    cudaGetSymbolAddress((void**)&rwl, g_rwl);
    cudaGetSymbolAddress((void**)&xh,  g_xh);
    cudaGetSymbolAddress((void**)&xl,  g_xl);
    cudaGetSymbolAddress((void**)&hh2, g_hh2);
    cudaGetSymbolAddress((void**)&hl2, g_hl2);

    cudaFuncSetAttribute(lstm_persistent_kernel,
                         cudaFuncAttributeMaxDynamicSharedMemorySize, LP_SMEM);
    cudaFuncSetAttribute(mm_bf16_kernel,
                         cudaFuncAttributeMaxDynamicSharedMemorySize, MMSMEM);

    zero_state_kernel<<<(BB * HID + 255) / 256, 256>>>();

    gather_kernel<<<MM, 128>>>(x, emb_W, xh, xl);

    split_kernel<<<4096, 256>>>(emb_W, ebh, ebl, (long)VOC * HID / 8);
    split_kernel<<<512,  256>>>(w_ih,  wh,  wl,  (long)GATES * HID / 8);
    split_kernel<<<512,  256>>>(w_hh,  rwh, rwl, (long)GATES * HID / 8);

    // x_proj TRANSPOSED: C[gate][m] = w_ih @ emb^T (bias folded into LSTM)
    {
        dim3 grid(GATES / 128, MM / 128);
        mm_bf16_kernel<<<grid, 256, MMSMEM>>>(wh, wl, xh, xl,
                                              (const float*)0, (const float*)0,
                                              xproj_p, MM, MM, HID, (float2*)0);
    }

    lstm_persistent_kernel<<<HID / 8, 256, LP_SMEM>>>(rwh, rwl, b_ih, b_hh);

    // decoder: logits = h_all @ emb_W^T + dec_b, with fused LSE partials
    {
        dim3 grid(MM / 128, NPART);
        mm_bf16_kernel<<<grid, 256, MMSMEM>>>(hh2, hl2, ebh, ebl, dec_b,
                                              (const float*)0, out, VOC, VOC, HID,
                                              lsepart_p);
    }

    lse_reduce_kernel<<<MM / 8, 256>>>(lsepart_p);
    sub_lse_kernel<<<MM, 256>>>(out);

    if (out_size >= MM * VOC + 2 * BB * HID)
        write_hidden_kernel<<<(2 * BB * HID + 255) / 256, 256>>>(out);
}

// round 15
// speedup vs baseline: 1.5382x; 1.0805x over previous
#include <cuda_runtime.h>
#include <cuda_bf16.h>
#include <math.h>
#include <stdint.h>

#define HID   1024
#define GATES 4096
#define BB    8
#define TT    256
#define MM    2048
#define VOC   50257
#define NPART ((VOC + 127) / 128)      // 393 decoder column tiles

typedef unsigned long long u64;

// ---------------- scratch ----------------
__device__ float g_xproj[(size_t)GATES * MM];       // TRANSPOSED: [gate][m]
__device__ float g_hbuf[2][BB * HID];
__device__ float g_c[BB * HID];
__device__ float g_lse[MM];
__device__ float2 g_lsepart[(size_t)MM * NPART];
__device__ int   g_bar_flags[128 * 32];             // one flag per CTA, 128B apart

// bf16 split operands
__device__ __nv_bfloat16 g_ebh[(size_t)VOC * HID];
__device__ __nv_bfloat16 g_ebl[(size_t)VOC * HID];
__device__ __nv_bfloat16 g_wh [(size_t)GATES * HID];
__device__ __nv_bfloat16 g_wl [(size_t)GATES * HID];
__device__ __nv_bfloat16 g_rwh[(size_t)GATES * HID];
__device__ __nv_bfloat16 g_rwl[(size_t)GATES * HID];
__device__ __nv_bfloat16 g_xh [(size_t)MM * HID];
__device__ __nv_bfloat16 g_xl [(size_t)MM * HID];
__device__ __nv_bfloat16 g_hh2[(size_t)MM * HID];
__device__ __nv_bfloat16 g_hl2[(size_t)MM * HID];

// ---------------- helpers ----------------
__device__ __forceinline__ void cpasync16(uint32_t dst, const void* src) {
    asm volatile("cp.async.cg.shared.global [%0], [%1], 16;\n" :: "r"(dst), "l"(src));
}
#define CP_COMMIT() asm volatile("cp.async.commit_group;\n")

__device__ __forceinline__ float fexp(float x) {
    float y = fmaxf(x * 1.4426950408889634f, -120.f);
    float n = rintf(y);
    float f = y - n;
    float p = 0.0013333558f;
    p = fmaf(p, f, 0.0096181291f);
    p = fmaf(p, f, 0.0555041087f);
    p = fmaf(p, f, 0.2402265069f);
    p = fmaf(p, f, 0.6931471806f);
    p = fmaf(p, f, 1.0f);
    return p * __int_as_float(((int)n + 127) << 23);
}

__device__ __forceinline__ void mma16816(float* d, const uint32_t* a, const uint32_t* b) {
    asm volatile(
        "mma.sync.aligned.m16n8k16.row.col.f32.bf16.bf16.f32 "
        "{%0,%1,%2,%3}, {%4,%5,%6,%7}, {%8,%9}, {%0,%1,%2,%3};"
        : "+f"(d[0]), "+f"(d[1]), "+f"(d[2]), "+f"(d[3])
        : "r"(a[0]), "r"(a[1]), "r"(a[2]), "r"(a[3]), "r"(b[0]), "r"(b[1]));
}

__device__ __forceinline__ uint32_t pkbf(float a, float b) {
    return ((uint32_t)__bfloat16_as_ushort(__float2bfloat16(b)) << 16)
         | __bfloat16_as_ushort(__float2bfloat16(a));
}
__device__ __forceinline__ void split8(float4 a, float4 b, uint4& ph, uint4& pl) {
    float h0 = __bfloat162float(__float2bfloat16(a.x));
    float h1 = __bfloat162float(__float2bfloat16(a.y));
    float h2 = __bfloat162float(__float2bfloat16(a.z));
    float h3 = __bfloat162float(__float2bfloat16(a.w));
    float h4 = __bfloat162float(__float2bfloat16(b.x));
    float h5 = __bfloat162float(__float2bfloat16(b.y));
    float h6 = __bfloat162float(__float2bfloat16(b.z));
    float h7 = __bfloat162float(__float2bfloat16(b.w));
    ph.x = pkbf(a.x, a.y); ph.y = pkbf(a.z, a.w);
    ph.z = pkbf(b.x, b.y); ph.w = pkbf(b.z, b.w);
    pl.x = pkbf(a.x - h0, a.y - h1); pl.y = pkbf(a.z - h2, a.w - h3);
    pl.z = pkbf(b.x - h4, b.y - h5); pl.w = pkbf(b.z - h6, b.w - h7);
}

// ---------------- small kernels ----------------
__global__ void zero_state_kernel() {
    int i = blockIdx.x * blockDim.x + threadIdx.x;
    if (i < BB * HID) { g_hbuf[0][i] = 0.f; g_c[i] = 0.f; }
    if (i < 128 * 32) g_bar_flags[i] = 0;
}

__global__ void gather_kernel(const int* __restrict__ x, const float* __restrict__ embW,
                              __nv_bfloat16* __restrict__ xh, __nv_bfloat16* __restrict__ xl) {
    int m = blockIdx.x;
    int t = m >> 3, b = m & 7;
    int tok = x[b * TT + t];
    const float4* src = (const float4*)(embW + (size_t)tok * HID);
    int i = threadIdx.x;
    float4 a = src[2 * i], c = src[2 * i + 1];
    uint4 ph, pl;
    split8(a, c, ph, pl);
    ((uint4*)(xh + (size_t)m * HID))[i] = ph;
    ((uint4*)(xl + (size_t)m * HID))[i] = pl;
}

__global__ void split_kernel(const float* __restrict__ s, __nv_bfloat16* __restrict__ h,
                             __nv_bfloat16* __restrict__ l, long n8) {
    long i = blockIdx.x * (long)blockDim.x + threadIdx.x;
    long st = (long)gridDim.x * blockDim.x;
    const float4* s4 = (const float4*)s;
    for (; i < n8; i += st) {
        float4 a = s4[2 * i], b = s4[2 * i + 1];
        uint4 ph, pl;
        split8(a, b, ph, pl);
        ((uint4*)h)[i] = ph;
        ((uint4*)l)[i] = pl;
    }
}

// ---------------- mma.sync split-bf16 NT GEMM (R11 config: BKP=40, KC=32) ----------------
#define BKP 40
#define BUF_B (128 * BKP * 2)
#define STAGE_B (4 * BUF_B)
#define MMSMEM (2 * STAGE_B)

__device__ __forceinline__ void stage_chunk_mma(
    char* smem, int stage, int tid, int kc,
    const __nv_bfloat16* Ah, const __nv_bfloat16* Al,
    const __nv_bfloat16* Bh, const __nv_bfloat16* Bl,
    int m0, int n0, int Nrows, int K)
{
    uint32_t sb = (uint32_t)__cvta_generic_to_shared(smem) + (uint32_t)stage * STAGE_B;
    #pragma unroll
    for (int i = 0; i < 8; i++) {
        int u = tid + 256 * i;
        int buf = u >> 9;
        int o = u & 511;
        int row = o >> 2;
        int col = (o & 3) * 8;
        const __nv_bfloat16* src;
        if (buf < 2) {
            src = ((buf == 0) ? Ah : Al) + (size_t)(m0 + row) * K + kc + col;
        } else {
            int n = n0 + row; if (n >= Nrows) n = Nrows - 1;
            src = ((buf == 2) ? Bh : Bl) + (size_t)n * K + kc + col;
        }
        cpasync16(sb + (uint32_t)(buf * BUF_B + (row * BKP + col) * 2), src);
    }
}

__global__ void __launch_bounds__(256, 2)
mm_bf16_kernel(const __nv_bfloat16* __restrict__ Ah, const __nv_bfloat16* __restrict__ Al,
               const __nv_bfloat16* __restrict__ Bh, const __nv_bfloat16* __restrict__ Bl,
               const float* __restrict__ bias1, const float* __restrict__ bias2,
               float* __restrict__ C, int Nrows, int ldc, int K,
               float2* __restrict__ lse_part)
{
    extern __shared__ char smem[];
    int tid = threadIdx.x;
    int wid = tid >> 5, lane = tid & 31;
    int m0 = blockIdx.x * 128;
    int n0 = blockIdx.y * 128;
    int m0w = (wid >> 2) * 64;
    int n0w = (wid & 3) * 32;
    const int NC = K / 32;

    float acc[4][4][4];
    #pragma unroll
    for (int mf = 0; mf < 4; mf++)
        #pragma unroll
        for (int nf = 0; nf < 4; nf++)
            #pragma unroll
            for (int e = 0; e < 4; e++) acc[mf][nf][e] = 0.f;

    stage_chunk_mma(smem, 0, tid, 0, Ah, Al, Bh, Bl, m0, n0, Nrows, K);
    CP_COMMIT();
    stage_chunk_mma(smem, 1, tid, 32, Ah, Al, Bh, Bl, m0, n0, Nrows, K);
    CP_COMMIT();

    int ar = lane >> 2;
    int ac = (lane & 3) * 2;

    for (int c = 0; c < NC; c++) {
        if (c < NC - 1) asm volatile("cp.async.wait_group 1;" ::: "memory");
        else            asm volatile("cp.async.wait_group 0;" ::: "memory");
        __syncthreads();

        const __nv_bfloat16* st = (const __nv_bfloat16*)(smem + (c & 1) * STAGE_B);
        const __nv_bfloat16* pAh = st;
        const __nv_bfloat16* pAl = st + 128 * BKP;
        const __nv_bfloat16* pBh = st + 2 * 128 * BKP;
        const __nv_bfloat16* pBl = st + 3 * 128 * BKP;

        #pragma unroll
        for (int ks = 0; ks < 32; ks += 16) {
            uint32_t fAh[4][4], fAl[4][4], fBh[4][2], fBl[4][2];
            #pragma unroll
            for (int mf = 0; mf < 4; mf++) {
                int r = m0w + mf * 16 + ar;
                int cc = ks + ac;
                fAh[mf][0] = *(const uint32_t*)(pAh + r * BKP + cc);
                fAh[mf][1] = *(const uint32_t*)(pAh + (r + 8) * BKP + cc);
                fAh[mf][2] = *(const uint32_t*)(pAh + r * BKP + cc + 8);
                fAh[mf][3] = *(const uint32_t*)(pAh + (r + 8) * BKP + cc + 8);
                fAl[mf][0] = *(const uint32_t*)(pAl + r * BKP + cc);
                fAl[mf][1] = *(const uint32_t*)(pAl + (r + 8) * BKP + cc);
                fAl[mf][2] = *(const uint32_t*)(pAl + r * BKP + cc + 8);
                fAl[mf][3] = *(const uint32_t*)(pAl + (r + 8) * BKP + cc + 8);
            }
            #pragma unroll
            for (int nf = 0; nf < 4; nf++) {
                int n = n0w + nf * 8 + ar;
                int kk = ks + ac;
                fBh[nf][0] = *(const uint32_t*)(pBh + n * BKP + kk);
                fBh[nf][1] = *(const uint32_t*)(pBh + n * BKP + kk + 8);
                fBl[nf][0] = *(const uint32_t*)(pBl + n * BKP + kk);
                fBl[nf][1] = *(const uint32_t*)(pBl + n * BKP + kk + 8);
            }
            #pragma unroll
            for (int mf = 0; mf < 4; mf++)
                #pragma unroll
                for (int nf = 0; nf < 4; nf++) {
                    mma16816(acc[mf][nf], fAh[mf], fBh[nf]);
                    mma16816(acc[mf][nf], fAh[mf], fBl[nf]);
                    mma16816(acc[mf][nf], fAl[mf], fBh[nf]);
                }
        }
        __syncthreads();
        if (c + 2 < NC) {
            stage_chunk_mma(smem, c & 1, tid, (c + 2) * 32, Ah, Al, Bh, Bl, m0, n0, Nrows, K);
            CP_COMMIT();
        }
    }

    // epilogue: scalar stores + optional online (max, sumexp) per row
    float rmax[4][2], rsum[4][2];
    #pragma unroll
    for (int mf = 0; mf < 4; mf++) { rmax[mf][0] = rmax[mf][1] = -1e30f; rsum[mf][0] = rsum[mf][1] = 0.f; }

    #pragma unroll
    for (int mf = 0; mf < 4; mf++) {
        int row0 = m0 + m0w + mf * 16 + ar;
        float* r0p = C + (size_t)row0 * ldc;
        float* r1p = C + (size_t)(row0 + 8) * ldc;
        #pragma unroll
        for (int nf = 0; nf < 4; nf++) {
            int col = n0 + n0w + nf * 8 + ac;
            #pragma unroll
            for (int e = 0; e < 2; e++) {
                int cc = col + e;
                if (cc < Nrows) {
                    float bv = 0.f;
                    if (bias1) bv += bias1[cc];
                    if (bias2) bv += bias2[cc];
                    float v0 = acc[mf][nf][e] + bv;
                    float v1 = acc[mf][nf][2 + e] + bv;
                    r0p[cc] = v0;
                    r1p[cc] = v1;
                    if (lse_part) {
                        if (v0 > rmax[mf][0]) { rsum[mf][0] = rsum[mf][0] * fexp(rmax[mf][0] - v0) + 1.f; rmax[mf][0] = v0; }
                        else                  { rsum[mf][0] += fexp(v0 - rmax[mf][0]); }
                        if (v1 > rmax[mf][1]) { rsum[mf][1] = rsum[mf][1] * fexp(rmax[mf][1] - v1) + 1.f; rmax[mf][1] = v1; }
                        else                  { rsum[mf][1] += fexp(v1 - rmax[mf][1]); }
                    }
                }
            }
        }
    }

    if (lse_part) {
        #pragma unroll
        for (int mf = 0; mf < 4; mf++)
            #pragma unroll
            for (int h = 0; h < 2; h++) {
                float m = rmax[mf][h], s = rsum[mf][h];
                #pragma unroll
                for (int off = 1; off <= 2; off <<= 1) {
                    float m2 = __shfl_xor_sync(0xffffffffu, m, off);
                    float s2 = __shfl_xor_sync(0xffffffffu, s, off);
                    float mm = fmaxf(m, m2);
                    s = s * fexp(m - mm) + s2 * fexp(m2 - mm);
                    m = mm;
                }
                rmax[mf][h] = m; rsum[mf][h] = s;
            }
        __syncthreads();
        float2* sp = (float2*)smem;
        if ((lane & 3) == 0) {
            #pragma unroll
            for (int mf = 0; mf < 4; mf++)
                #pragma unroll
                for (int h = 0; h < 2; h++) {
                    int rc = m0w + mf * 16 + ar + h * 8;
                    sp[rc * 4 + (wid & 3)] = make_float2(rmax[mf][h], rsum[mf][h]);
                }
        }
        __syncthreads();
        if (tid < 128) {
            float m = -1e30f, s = 0.f;
            #pragma unroll
            for (int w = 0; w < 4; w++) {
                float2 p = sp[tid * 4 + w];
                float mm = fmaxf(m, p.x);
                s = s * fexp(m - mm) + p.y * fexp(p.x - mm);
                m = mm;
            }
            lse_part[(size_t)(m0 + tid) * NPART + blockIdx.y] = make_float2(m, s);
        }
    }
}

// ---------------- persistent LSTM ----------------
#define WPAD 1032
#define LP_SWH 0
#define LP_SWL 66048
#define LP_SHH 132096
#define LP_SHL 148608
#define LP_RED 165120
#define LP_GATES 173312
#define LP_BIAS 174336
#define LP_SMEM 174464

__global__ void __launch_bounds__(256)
lstm_persistent_kernel(const __nv_bfloat16* __restrict__ rwh,
                       const __nv_bfloat16* __restrict__ rwl,
                       const float* __restrict__ b_ih,
                       const float* __restrict__ b_hh)
{
    extern __shared__ char smraw[];
    __nv_bfloat16* swh = (__nv_bfloat16*)(smraw + LP_SWH);
    __nv_bfloat16* swl = (__nv_bfloat16*)(smraw + LP_SWL);
    __nv_bfloat16* shh = (__nv_bfloat16*)(smraw + LP_SHH);
    __nv_bfloat16* shl = (__nv_bfloat16*)(smraw + LP_SHL);
    float* red      = (float*)(smraw + LP_RED);
    float* sm_gates = (float*)(smraw + LP_GATES);
    float* sm_bias  = (float*)(smraw + LP_BIAS);

    int tid = threadIdx.x;
    int jb = blockIdx.x * 8;

    {
        uint32_t sb = (uint32_t)__cvta_generic_to_shared(smraw);
        #pragma unroll
        for (int i = 0; i < 32; i++) {
            int u = tid + 256 * i;
            int buf = u >> 12;
            int o = u & 4095;
            int row = o >> 7;
            int ch = o & 127;
            int g = row >> 3, jl = row & 7;
            const __nv_bfloat16* src = (buf ? rwl : rwh)
                + (size_t)(g * HID + jb + jl) * HID + ch * 8;
            cpasync16(sb + (uint32_t)(buf * LP_SWL + row * (WPAD * 2) + ch * 16), src);
        }
        CP_COMMIT();
        if (tid < 32) {
            int g = tid >> 3, jl = tid & 7;
            sm_bias[tid] = b_ih[g * HID + jb + jl] + b_hh[g * HID + jb + jl];
        }
        asm volatile("cp.async.wait_group 0;\n" ::: "memory");
        __syncthreads();
    }

    int wid = tid >> 5, lane = tid & 31;
    int ar = lane >> 2;
    int ac = (lane & 3) * 2;
    int ejl = tid >> 3, eb = tid & 7;
    float c_reg = 0.f;

    const float* xpp;
    {
        int prow = tid >> 3, pb = tid & 7;
        int pg = prow >> 3, pjl = prow & 7;
        xpp = g_xproj + (size_t)(pg * HID + jb + pjl) * MM + pb;
    }

    for (int t = 0; t < TT; t++) {
        const float* hprev = g_hbuf[t & 1];
        float* hnext = g_hbuf[(t + 1) & 1];

        float xp_pre = __ldcg(xpp + t * BB);

        {
            const float4* hp4 = (const float4*)hprev;
            #pragma unroll
            for (int i = 0; i < 8; i++) {
                int f4 = tid + 256 * i;
                float4 v = __ldcg(hp4 + f4);
                int batch = f4 >> 8;
                int k = (f4 & 255) * 4;
                int off = batch * WPAD + k;
                float h0 = __bfloat162float(__float2bfloat16(v.x));
                float h1 = __bfloat162float(__float2bfloat16(v.y));
                float h2 = __bfloat162float(__float2bfloat16(v.z));
                float h3 = __bfloat162float(__float2bfloat16(v.w));
                uint2 ph, pl;
                ph.x = pkbf(v.x, v.y);
                ph.y = pkbf(v.z, v.w);
                pl.x = pkbf(v.x - h0, v.y - h1);
                pl.y = pkbf(v.z - h2, v.w - h3);
                *(uint2*)(shh + off) = ph;
                *(uint2*)(shl + off) = pl;
            }
        }
        __syncthreads();

        float acc[2][4];
        #pragma unroll
        for (int mt = 0; mt < 2; mt++)
            #pragma unroll
            for (int e = 0; e < 4; e++) acc[mt][e] = 0.f;

        #pragma unroll
        for (int ks8 = 0; ks8 < 8; ks8++) {
            int kk = wid * 128 + ks8 * 16;
            uint32_t bh[2], bl[2];
            bh[0] = *(const uint32_t*)(shh + ar * WPAD + kk + ac);
            bh[1] = *(const uint32_t*)(shh + ar * WPAD + kk + ac + 8);
            bl[0] = *(const uint32_t*)(shl + ar * WPAD + kk + ac);
            bl[1] = *(const uint32_t*)(shl + ar * WPAD + kk + ac + 8);
            #pragma unroll
            for (int mt = 0; mt < 2; mt++) {
                int r = mt * 16 + ar;
                uint32_t ah[4], al[4];
                ah[0] = *(const uint32_t*)(swh + r * WPAD + kk + ac);
                ah[1] = *(const uint32_t*)(swh + (r + 8) * WPAD + kk + ac);
                ah[2] = *(const uint32_t*)(swh + r * WPAD + kk + ac + 8);
                ah[3] = *(const uint32_t*)(swh + (r + 8) * WPAD + kk + ac + 8);
                al[0] = *(const uint32_t*)(swl + r * WPAD + kk + ac);
                al[1] = *(const uint32_t*)(swl + (r + 8) * WPAD + kk + ac);
                al[2] = *(const uint32_t*)(swl + r * WPAD + kk + ac + 8);
                al[3] = *(const uint32_t*)(swl + (r + 8) * WPAD + kk + ac + 8);
                mma16816(acc[mt], ah, bh);
                mma16816(acc[mt], ah, bl);
                mma16816(acc[mt], al, bh);
            }
        }

        #pragma unroll
        for (int mt = 0; mt < 2; mt++)
            #pragma unroll
            for (int e = 0; e < 4; e++) {
                int row = mt * 16 + ar + ((e & 2) ? 8 : 0);
                int b = ac + (e & 1);
                red[row * 64 + b * 8 + wid] = acc[mt][e];
            }
        __syncthreads();

        {
            float4 p0 = *(float4*)(red + tid * 8);
            float4 p1 = *(float4*)(red + tid * 8 + 4);
            sm_gates[tid] = ((p0.x + p0.y) + (p0.z + p0.w))
                          + ((p1.x + p1.y) + (p1.z + p1.w))
                          + xp_pre + sm_bias[tid >> 3];
        }
        __syncthreads();

        if (tid < 64) {
            int j = jb + ejl;
            float gi = sm_gates[(0 * 8 + ejl) * 8 + eb];
            float gf = sm_gates[(1 * 8 + ejl) * 8 + eb];
            float gg = sm_gates[(2 * 8 + ejl) * 8 + eb];
            float go = sm_gates[(3 * 8 + ejl) * 8 + eb];
            gi = 1.f / (1.f + expf(-gi));
            gf = 1.f / (1.f + expf(-gf));
            gg = tanhf(gg);
            go = 1.f / (1.f + expf(-go));
            c_reg = gf * c_reg + gi * gg;
            float h = go * tanhf(c_reg);
            hnext[eb * HID + j] = h;
            size_t di = ((size_t)eb * TT + t) * HID + j;
            float hh = __bfloat162float(__float2bfloat16(h));
            g_hh2[di] = __float2bfloat16(h);
            g_hl2[di] = __float2bfloat16(h - hh);
            if (t == TT - 1) g_c[eb * HID + j] = c_reg;
        }

        // flat all-poll grid barrier
        __syncthreads();
        __threadfence();
        if (tid == 0)
            *(volatile int*)&g_bar_flags[blockIdx.x * 32] = t + 1;
        if (wid == 0) {
            int idx = lane * 4;
            for (;;) {
                int ok = 1;
                #pragma unroll
                for (int q = 0; q < 4; q++)
                    ok &= (*(volatile int*)&g_bar_flags[(idx + q) * 32] >= t + 1);
                if (__all_sync(0xffffffffu, ok)) break;
            }
        }
        __syncthreads();
    }
}

// ---------------- LSE partial reduce + subtract ----------------
__global__ void __launch_bounds__(256)
lse_reduce_kernel(const float2* __restrict__ part)
{
    int row = blockIdx.x * 8 + (threadIdx.x >> 5);
    int lane = threadIdx.x & 31;
    float m = -1e30f, s = 0.f;
    for (int i = lane; i < NPART; i += 32) {
        float2 p = part[(size_t)row * NPART + i];
        float mm = fmaxf(m, p.x);
        s = s * fexp(m - mm) + p.y * fexp(p.x - mm);
        m = mm;
    }
    #pragma unroll
    for (int off = 16; off; off >>= 1) {
        float m2 = __shfl_xor_sync(0xffffffffu, m, off);
        float s2 = __shfl_xor_sync(0xffffffffu, s, off);
        float mm = fmaxf(m, m2);
        s = s * fexp(m - mm) + s2 * fexp(m2 - mm);
        m = mm;
    }
    if (lane == 0) g_lse[row] = m + logf(s);
}

__global__ void __launch_bounds__(256)
sub_lse_kernel(float* __restrict__ out)
{
    int row = blockIdx.x;
    float l = g_lse[row];
    float* p = out + (size_t)row * VOC;
    // peel to 16B alignment (row*VOC may be odd)
    int head = (int)(((16 - ((uintptr_t)p & 15)) & 15) >> 2);
    if (head > VOC) head = VOC;
    if (threadIdx.x < head) p[threadIdx.x] -= l;
    int n4 = (VOC - head) >> 2;
    float4* p4 = (float4*)(p + head);
    for (int i = threadIdx.x; i < n4; i += 256) {
        float4 v = p4[i];
        v.x -= l; v.y -= l; v.z -= l; v.w -= l;
        p4[i] = v;
    }
    int tail = head + n4 * 4;
    int rem = VOC - tail;
    if ((int)threadIdx.x < rem) p[tail + threadIdx.x] -= l;
}

__global__ void write_hidden_kernel(float* __restrict__ out)
{
    int i = blockIdx.x * blockDim.x + threadIdx.x;
    size_t base = (size_t)MM * VOC;
    if (i < BB * HID)               out[base + i] = g_hbuf[0][i];
    else if (i < 2 * BB * HID)      out[base + i] = g_c[i - BB * HID];
}

// ---------------- launcher ----------------
extern "C" void kernel_launch(void* const* d_in, const int* in_sizes, int n_in,
                              void* d_out, int out_size)
{
    const int*   x     = (const int*)  d_in[0];
    const float* emb_W = (const float*)d_in[1];
    const float* w_ih  = (const float*)d_in[2];
    const float* w_hh  = (const float*)d_in[3];
    const float* b_ih  = (const float*)d_in[4];
    const float* b_hh  = (const float*)d_in[5];
    const float* dec_b = (const float*)d_in[6];
    float* out = (float*)d_out;

    float* xproj_p; cudaGetSymbolAddress((void**)&xproj_p, g_xproj);
    float2* lsepart_p; cudaGetSymbolAddress((void**)&lsepart_p, g_lsepart);
    __nv_bfloat16 *ebh, *ebl, *wh, *wl, *rwh, *rwl, *xh, *xl, *hh2, *hl2;
    cudaGetSymbolAddress((void**)&ebh, g_ebh);
    cudaGetSymbolAddress((void**)&ebl, g_ebl);
    cudaGetSymbolAddress((void**)&wh,  g_wh);
    cudaGetSymbolAddress((void**)&wl,  g_wl);
    cudaGetSymbolAddress((void**)&rwh, g_rwh);
    cudaGetSymbolAddress((void**)&rwl, g_rwl);
    cudaGetSymbolAddress((void**)&xh,  g_xh);
    cudaGetSymbolAddress((void**)&xl,  g_xl);
    cudaGetSymbolAddress((void**)&hh2, g_hh2);
    cudaGetSymbolAddress((void**)&hl2, g_hl2);

    cudaFuncSetAttribute(lstm_persistent_kernel,
                         cudaFuncAttributeMaxDynamicSharedMemorySize, LP_SMEM);
    cudaFuncSetAttribute(mm_bf16_kernel,
                         cudaFuncAttributeMaxDynamicSharedMemorySize, MMSMEM);

    zero_state_kernel<<<(BB * HID + 255) / 256, 256>>>();

    gather_kernel<<<MM, 128>>>(x, emb_W, xh, xl);

    split_kernel<<<4096, 256>>>(emb_W, ebh, ebl, (long)VOC * HID / 8);
    split_kernel<<<512,  256>>>(w_ih,  wh,  wl,  (long)GATES * HID / 8);
    split_kernel<<<512,  256>>>(w_hh,  rwh, rwl, (long)GATES * HID / 8);

    // x_proj TRANSPOSED: C[gate][m] = w_ih @ emb^T (bias folded into LSTM)
    {
        dim3 grid(GATES / 128, MM / 128);
        mm_bf16_kernel<<<grid, 256, MMSMEM>>>(wh, wl, xh, xl,
                                              (const float*)0, (const float*)0,
                                              xproj_p, MM, MM, HID, (float2*)0);
    }

    lstm_persistent_kernel<<<HID / 8, 256, LP_SMEM>>>(rwh, rwl, b_ih, b_hh);

    // decoder: logits = h_all @ emb_W^T + dec_b, with fused LSE partials
    {
        dim3 grid(MM / 128, NPART);
        mm_bf16_kernel<<<grid, 256, MMSMEM>>>(hh2, hl2, ebh, ebl, dec_b,
                                              (const float*)0, out, VOC, VOC, HID,
                                              lsepart_p);
    }

    lse_reduce_kernel<<<MM / 8, 256>>>(lsepart_p);
    sub_lse_kernel<<<MM, 256>>>(out);

    if (out_size >= MM * VOC + 2 * BB * HID)
        write_hidden_kernel<<<(2 * BB * HID + 255) / 256, 256>>>(out);
}

// round 16
// speedup vs baseline: 1.5409x; 1.0018x over previous
#include <cuda_runtime.h>
#include <cuda_bf16.h>
#include <math.h>
#include <stdint.h>

#define HID   1024
#define GATES 4096
#define BB    8
#define TT    256
#define MM    2048
#define VOC   50257
#define NPART ((VOC + 127) / 128)      // 393 decoder column tiles

typedef unsigned long long u64;

// ---------------- scratch ----------------
__device__ float g_xproj[(size_t)GATES * MM];       // TRANSPOSED: [gate][m]
__device__ float g_hbuf[2][BB * HID];
__device__ float g_c[BB * HID];
__device__ float g_lse[MM];
__device__ float2 g_lsepart[(size_t)MM * NPART];
__device__ int   g_bar_flags[128 * 32];             // one flag per CTA, 128B apart

// bf16 split operands
__device__ __nv_bfloat16 g_ebh[(size_t)VOC * HID];
__device__ __nv_bfloat16 g_ebl[(size_t)VOC * HID];
__device__ __nv_bfloat16 g_wh [(size_t)GATES * HID];
__device__ __nv_bfloat16 g_wl [(size_t)GATES * HID];
__device__ __nv_bfloat16 g_rwh[(size_t)GATES * HID];
__device__ __nv_bfloat16 g_rwl[(size_t)GATES * HID];
__device__ __nv_bfloat16 g_xh [(size_t)MM * HID];
__device__ __nv_bfloat16 g_xl [(size_t)MM * HID];
__device__ __nv_bfloat16 g_hh2[(size_t)MM * HID];
__device__ __nv_bfloat16 g_hl2[(size_t)MM * HID];

// ---------------- helpers ----------------
__device__ __forceinline__ void cpasync16(uint32_t dst, const void* src) {
    asm volatile("cp.async.cg.shared.global [%0], [%1], 16;\n" :: "r"(dst), "l"(src));
}
#define CP_COMMIT() asm volatile("cp.async.commit_group;\n")

__device__ __forceinline__ float fexp(float x) {
    float y = fmaxf(x * 1.4426950408889634f, -120.f);
    float n = rintf(y);
    float f = y - n;
    float p = 0.0013333558f;
    p = fmaf(p, f, 0.0096181291f);
    p = fmaf(p, f, 0.0555041087f);
    p = fmaf(p, f, 0.2402265069f);
    p = fmaf(p, f, 0.6931471806f);
    p = fmaf(p, f, 1.0f);
    return p * __int_as_float(((int)n + 127) << 23);
}

__device__ __forceinline__ void mma16816(float* d, const uint32_t* a, const uint32_t* b) {
    asm volatile(
        "mma.sync.aligned.m16n8k16.row.col.f32.bf16.bf16.f32 "
        "{%0,%1,%2,%3}, {%4,%5,%6,%7}, {%8,%9}, {%0,%1,%2,%3};"
        : "+f"(d[0]), "+f"(d[1]), "+f"(d[2]), "+f"(d[3])
        : "r"(a[0]), "r"(a[1]), "r"(a[2]), "r"(a[3]), "r"(b[0]), "r"(b[1]));
}

__device__ __forceinline__ uint32_t pkbf(float a, float b) {
    return ((uint32_t)__bfloat16_as_ushort(__float2bfloat16(b)) << 16)
         | __bfloat16_as_ushort(__float2bfloat16(a));
}
__device__ __forceinline__ void split8(float4 a, float4 b, uint4& ph, uint4& pl) {
    float h0 = __bfloat162float(__float2bfloat16(a.x));
    float h1 = __bfloat162float(__float2bfloat16(a.y));
    float h2 = __bfloat162float(__float2bfloat16(a.z));
    float h3 = __bfloat162float(__float2bfloat16(a.w));
    float h4 = __bfloat162float(__float2bfloat16(b.x));
    float h5 = __bfloat162float(__float2bfloat16(b.y));
    float h6 = __bfloat162float(__float2bfloat16(b.z));
    float h7 = __bfloat162float(__float2bfloat16(b.w));
    ph.x = pkbf(a.x, a.y); ph.y = pkbf(a.z, a.w);
    ph.z = pkbf(b.x, b.y); ph.w = pkbf(b.z, b.w);
    pl.x = pkbf(a.x - h0, a.y - h1); pl.y = pkbf(a.z - h2, a.w - h3);
    pl.z = pkbf(b.x - h4, b.y - h5); pl.w = pkbf(b.z - h6, b.w - h7);
}

// ---------------- gather + state-zero fused ----------------
__global__ void gather_kernel(const int* __restrict__ x, const float* __restrict__ embW,
                              __nv_bfloat16* __restrict__ xh, __nv_bfloat16* __restrict__ xl) {
    int m = blockIdx.x;
    int i = threadIdx.x;
    // fused init: blocks 64..95 zero h0/flags (in addition to their gather work)
    if (m < 64) {
        g_hbuf[0][m * 128 + i] = 0.f;
    } else if (m < 96) {
        g_bar_flags[(m - 64) * 128 + i] = 0;
    }
    int t = m >> 3, b = m & 7;
    int tok = x[b * TT + t];
    const float4* src = (const float4*)(embW + (size_t)tok * HID);
    float4 a = src[2 * i], c = src[2 * i + 1];
    uint4 ph, pl;
    split8(a, c, ph, pl);
    ((uint4*)(xh + (size_t)m * HID))[i] = ph;
    ((uint4*)(xl + (size_t)m * HID))[i] = pl;
}

__global__ void split_kernel(const float* __restrict__ s, __nv_bfloat16* __restrict__ h,
                             __nv_bfloat16* __restrict__ l, long n8) {
    long i = blockIdx.x * (long)blockDim.x + threadIdx.x;
    long st = (long)gridDim.x * blockDim.x;
    const float4* s4 = (const float4*)s;
    for (; i < n8; i += st) {
        float4 a = s4[2 * i], b = s4[2 * i + 1];
        uint4 ph, pl;
        split8(a, b, ph, pl);
        ((uint4*)h)[i] = ph;
        ((uint4*)l)[i] = pl;
    }
}

// ---------------- mma.sync split-bf16 NT GEMM (FROZEN: BKP=40, KC=32) ----------------
#define BKP 40
#define BUF_B (128 * BKP * 2)
#define STAGE_B (4 * BUF_B)
#define MMSMEM (2 * STAGE_B)

__device__ __forceinline__ void stage_chunk_mma(
    char* smem, int stage, int tid, int kc,
    const __nv_bfloat16* Ah, const __nv_bfloat16* Al,
    const __nv_bfloat16* Bh, const __nv_bfloat16* Bl,
    int m0, int n0, int Nrows, int K)
{
    uint32_t sb = (uint32_t)__cvta_generic_to_shared(smem) + (uint32_t)stage * STAGE_B;
    #pragma unroll
    for (int i = 0; i < 8; i++) {
        int u = tid + 256 * i;
        int buf = u >> 9;
        int o = u & 511;
        int row = o >> 2;
        int col = (o & 3) * 8;
        const __nv_bfloat16* src;
        if (buf < 2) {
            src = ((buf == 0) ? Ah : Al) + (size_t)(m0 + row) * K + kc + col;
        } else {
            int n = n0 + row; if (n >= Nrows) n = Nrows - 1;
            src = ((buf == 2) ? Bh : Bl) + (size_t)n * K + kc + col;
        }
        cpasync16(sb + (uint32_t)(buf * BUF_B + (row * BKP + col) * 2), src);
    }
}

__global__ void __launch_bounds__(256, 2)
mm_bf16_kernel(const __nv_bfloat16* __restrict__ Ah, const __nv_bfloat16* __restrict__ Al,
               const __nv_bfloat16* __restrict__ Bh, const __nv_bfloat16* __restrict__ Bl,
               const float* __restrict__ bias1, const float* __restrict__ bias2,
               float* __restrict__ C, int Nrows, int ldc, int K,
               float2* __restrict__ lse_part)
{
    extern __shared__ char smem[];
    int tid = threadIdx.x;
    int wid = tid >> 5, lane = tid & 31;
    int m0 = blockIdx.x * 128;
    int n0 = blockIdx.y * 128;
    int m0w = (wid >> 2) * 64;
    int n0w = (wid & 3) * 32;
    const int NC = K / 32;

    float acc[4][4][4];
    #pragma unroll
    for (int mf = 0; mf < 4; mf++)
        #pragma unroll
        for (int nf = 0; nf < 4; nf++)
            #pragma unroll
            for (int e = 0; e < 4; e++) acc[mf][nf][e] = 0.f;

    stage_chunk_mma(smem, 0, tid, 0, Ah, Al, Bh, Bl, m0, n0, Nrows, K);
    CP_COMMIT();
    stage_chunk_mma(smem, 1, tid, 32, Ah, Al, Bh, Bl, m0, n0, Nrows, K);
    CP_COMMIT();

    int ar = lane >> 2;
    int ac = (lane & 3) * 2;

    for (int c = 0; c < NC; c++) {
        if (c < NC - 1) asm volatile("cp.async.wait_group 1;" ::: "memory");
        else            asm volatile("cp.async.wait_group 0;" ::: "memory");
        __syncthreads();

        const __nv_bfloat16* st = (const __nv_bfloat16*)(smem + (c & 1) * STAGE_B);
        const __nv_bfloat16* pAh = st;
        const __nv_bfloat16* pAl = st + 128 * BKP;
        const __nv_bfloat16* pBh = st + 2 * 128 * BKP;
        const __nv_bfloat16* pBl = st + 3 * 128 * BKP;

        #pragma unroll
        for (int ks = 0; ks < 32; ks += 16) {
            uint32_t fAh[4][4], fAl[4][4], fBh[4][2], fBl[4][2];
            #pragma unroll
            for (int mf = 0; mf < 4; mf++) {
                int r = m0w + mf * 16 + ar;
                int cc = ks + ac;
                fAh[mf][0] = *(const uint32_t*)(pAh + r * BKP + cc);
                fAh[mf][1] = *(const uint32_t*)(pAh + (r + 8) * BKP + cc);
                fAh[mf][2] = *(const uint32_t*)(pAh + r * BKP + cc + 8);
                fAh[mf][3] = *(const uint32_t*)(pAh + (r + 8) * BKP + cc + 8);
                fAl[mf][0] = *(const uint32_t*)(pAl + r * BKP + cc);
                fAl[mf][1] = *(const uint32_t*)(pAl + (r + 8) * BKP + cc);
                fAl[mf][2] = *(const uint32_t*)(pAl + r * BKP + cc + 8);
                fAl[mf][3] = *(const uint32_t*)(pAl + (r + 8) * BKP + cc + 8);
            }
            #pragma unroll
            for (int nf = 0; nf < 4; nf++) {
                int n = n0w + nf * 8 + ar;
                int kk = ks + ac;
                fBh[nf][0] = *(const uint32_t*)(pBh + n * BKP + kk);
                fBh[nf][1] = *(const uint32_t*)(pBh + n * BKP + kk + 8);
                fBl[nf][0] = *(const uint32_t*)(pBl + n * BKP + kk);
                fBl[nf][1] = *(const uint32_t*)(pBl + n * BKP + kk + 8);
            }
            #pragma unroll
            for (int mf = 0; mf < 4; mf++)
                #pragma unroll
                for (int nf = 0; nf < 4; nf++) {
                    mma16816(acc[mf][nf], fAh[mf], fBh[nf]);
                    mma16816(acc[mf][nf], fAh[mf], fBl[nf]);
                    mma16816(acc[mf][nf], fAl[mf], fBh[nf]);
                }
        }
        __syncthreads();
        if (c + 2 < NC) {
            stage_chunk_mma(smem, c & 1, tid, (c + 2) * 32, Ah, Al, Bh, Bl, m0, n0, Nrows, K);
            CP_COMMIT();
        }
    }

    // epilogue: scalar stores + optional online (max, sumexp) per row
    float rmax[4][2], rsum[4][2];
    #pragma unroll
    for (int mf = 0; mf < 4; mf++) { rmax[mf][0] = rmax[mf][1] = -1e30f; rsum[mf][0] = rsum[mf][1] = 0.f; }

    #pragma unroll
    for (int mf = 0; mf < 4; mf++) {
        int row0 = m0 + m0w + mf * 16 + ar;
        float* r0p = C + (size_t)row0 * ldc;
        float* r1p = C + (size_t)(row0 + 8) * ldc;
        #pragma unroll
        for (int nf = 0; nf < 4; nf++) {
            int col = n0 + n0w + nf * 8 + ac;
            #pragma unroll
            for (int e = 0; e < 2; e++) {
                int cc = col + e;
                if (cc < Nrows) {
                    float bv = 0.f;
                    if (bias1) bv += bias1[cc];
                    if (bias2) bv += bias2[cc];
                    float v0 = acc[mf][nf][e] + bv;
                    float v1 = acc[mf][nf][2 + e] + bv;
                    r0p[cc] = v0;
                    r1p[cc] = v1;
                    if (lse_part) {
                        if (v0 > rmax[mf][0]) { rsum[mf][0] = rsum[mf][0] * fexp(rmax[mf][0] - v0) + 1.f; rmax[mf][0] = v0; }
                        else                  { rsum[mf][0] += fexp(v0 - rmax[mf][0]); }
                        if (v1 > rmax[mf][1]) { rsum[mf][1] = rsum[mf][1] * fexp(rmax[mf][1] - v1) + 1.f; rmax[mf][1] = v1; }
                        else                  { rsum[mf][1] += fexp(v1 - rmax[mf][1]); }
                    }
                }
            }
        }
    }

    if (lse_part) {
        #pragma unroll
        for (int mf = 0; mf < 4; mf++)
            #pragma unroll
            for (int h = 0; h < 2; h++) {
                float m = rmax[mf][h], s = rsum[mf][h];
                #pragma unroll
                for (int off = 1; off <= 2; off <<= 1) {
                    float m2 = __shfl_xor_sync(0xffffffffu, m, off);
                    float s2 = __shfl_xor_sync(0xffffffffu, s, off);
                    float mm = fmaxf(m, m2);
                    s = s * fexp(m - mm) + s2 * fexp(m2 - mm);
                    m = mm;
                }
                rmax[mf][h] = m; rsum[mf][h] = s;
            }
        __syncthreads();
        float2* sp = (float2*)smem;
        if ((lane & 3) == 0) {
            #pragma unroll
            for (int mf = 0; mf < 4; mf++)
                #pragma unroll
                for (int h = 0; h < 2; h++) {
                    int rc = m0w + mf * 16 + ar + h * 8;
                    sp[rc * 4 + (wid & 3)] = make_float2(rmax[mf][h], rsum[mf][h]);
                }
        }
        __syncthreads();
        if (tid < 128) {
            float m = -1e30f, s = 0.f;
            #pragma unroll
            for (int w = 0; w < 4; w++) {
                float2 p = sp[tid * 4 + w];
                float mm = fmaxf(m, p.x);
                s = s * fexp(m - mm) + p.y * fexp(p.x - mm);
                m = mm;
            }
            lse_part[(size_t)(m0 + tid) * NPART + blockIdx.y] = make_float2(m, s);
        }
    }
}

// ---------------- persistent LSTM ----------------
#define WPAD 1032
#define LP_SWH 0
#define LP_SWL 66048
#define LP_SHH 132096
#define LP_SHL 148608
#define LP_RED 165120
#define LP_GATES 173312
#define LP_BIAS 174336
#define LP_SMEM 174464

__global__ void __launch_bounds__(256)
lstm_persistent_kernel(const __nv_bfloat16* __restrict__ rwh,
                       const __nv_bfloat16* __restrict__ rwl,
                       const float* __restrict__ b_ih,
                       const float* __restrict__ b_hh)
{
    extern __shared__ char smraw[];
    __nv_bfloat16* swh = (__nv_bfloat16*)(smraw + LP_SWH);
    __nv_bfloat16* swl = (__nv_bfloat16*)(smraw + LP_SWL);
    __nv_bfloat16* shh = (__nv_bfloat16*)(smraw + LP_SHH);
    __nv_bfloat16* shl = (__nv_bfloat16*)(smraw + LP_SHL);
    float* red      = (float*)(smraw + LP_RED);
    float* sm_gates = (float*)(smraw + LP_GATES);
    float* sm_bias  = (float*)(smraw + LP_BIAS);

    int tid = threadIdx.x;
    int jb = blockIdx.x * 8;

    {
        uint32_t sb = (uint32_t)__cvta_generic_to_shared(smraw);
        #pragma unroll
        for (int i = 0; i < 32; i++) {
            int u = tid + 256 * i;
            int buf = u >> 12;
            int o = u & 4095;
            int row = o >> 7;
            int ch = o & 127;
            int g = row >> 3, jl = row & 7;
            const __nv_bfloat16* src = (buf ? rwl : rwh)
                + (size_t)(g * HID + jb + jl) * HID + ch * 8;
            cpasync16(sb + (uint32_t)(buf * LP_SWL + row * (WPAD * 2) + ch * 16), src);
        }
        CP_COMMIT();
        if (tid < 32) {
            int g = tid >> 3, jl = tid & 7;
            sm_bias[tid] = b_ih[g * HID + jb + jl] + b_hh[g * HID + jb + jl];
        }
        asm volatile("cp.async.wait_group 0;\n" ::: "memory");
        __syncthreads();
    }

    int wid = tid >> 5, lane = tid & 31;
    int ar = lane >> 2;
    int ac = (lane & 3) * 2;
    int ejl = tid >> 3, eb = tid & 7;
    float c_reg = 0.f;

    const float* xpp;
    {
        int prow = tid >> 3, pb = tid & 7;
        int pg = prow >> 3, pjl = prow & 7;
        xpp = g_xproj + (size_t)(pg * HID + jb + pjl) * MM + pb;
    }

    for (int t = 0; t < TT; t++) {
        const float* hprev = g_hbuf[t & 1];
        float* hnext = g_hbuf[(t + 1) & 1];

        float xp_pre = __ldcg(xpp + t * BB);

        {
            const float4* hp4 = (const float4*)hprev;
            #pragma unroll
            for (int i = 0; i < 8; i++) {
                int f4 = tid + 256 * i;
                float4 v = __ldcg(hp4 + f4);
                int batch = f4 >> 8;
                int k = (f4 & 255) * 4;
                int off = batch * WPAD + k;
                float h0 = __bfloat162float(__float2bfloat16(v.x));
                float h1 = __bfloat162float(__float2bfloat16(v.y));
                float h2 = __bfloat162float(__float2bfloat16(v.z));
                float h3 = __bfloat162float(__float2bfloat16(v.w));
                uint2 ph, pl;
                ph.x = pkbf(v.x, v.y);
                ph.y = pkbf(v.z, v.w);
                pl.x = pkbf(v.x - h0, v.y - h1);
                pl.y = pkbf(v.z - h2, v.w - h3);
                *(uint2*)(shh + off) = ph;
                *(uint2*)(shl + off) = pl;
            }
        }
        __syncthreads();

        float acc[2][4];
        #pragma unroll
        for (int mt = 0; mt < 2; mt++)
            #pragma unroll
            for (int e = 0; e < 4; e++) acc[mt][e] = 0.f;

        #pragma unroll
        for (int ks8 = 0; ks8 < 8; ks8++) {
            int kk = wid * 128 + ks8 * 16;
            uint32_t bh[2], bl[2];
            bh[0] = *(const uint32_t*)(shh + ar * WPAD + kk + ac);
            bh[1] = *(const uint32_t*)(shh + ar * WPAD + kk + ac + 8);
            bl[0] = *(const uint32_t*)(shl + ar * WPAD + kk + ac);
            bl[1] = *(const uint32_t*)(shl + ar * WPAD + kk + ac + 8);
            #pragma unroll
            for (int mt = 0; mt < 2; mt++) {
                int r = mt * 16 + ar;
                uint32_t ah[4], al[4];
                ah[0] = *(const uint32_t*)(swh + r * WPAD + kk + ac);
                ah[1] = *(const uint32_t*)(swh + (r + 8) * WPAD + kk + ac);
                ah[2] = *(const uint32_t*)(swh + r * WPAD + kk + ac + 8);
                ah[3] = *(const uint32_t*)(swh + (r + 8) * WPAD + kk + ac + 8);
                al[0] = *(const uint32_t*)(swl + r * WPAD + kk + ac);
                al[1] = *(const uint32_t*)(swl + (r + 8) * WPAD + kk + ac);
                al[2] = *(const uint32_t*)(swl + r * WPAD + kk + ac + 8);
                al[3] = *(const uint32_t*)(swl + (r + 8) * WPAD + kk + ac + 8);
                mma16816(acc[mt], ah, bh);
                mma16816(acc[mt], ah, bl);
                mma16816(acc[mt], al, bh);
            }
        }

        #pragma unroll
        for (int mt = 0; mt < 2; mt++)
            #pragma unroll
            for (int e = 0; e < 4; e++) {
                int row = mt * 16 + ar + ((e & 2) ? 8 : 0);
                int b = ac + (e & 1);
                red[row * 64 + b * 8 + wid] = acc[mt][e];
            }
        __syncthreads();

        {
            float4 p0 = *(float4*)(red + tid * 8);
            float4 p1 = *(float4*)(red + tid * 8 + 4);
            sm_gates[tid] = ((p0.x + p0.y) + (p0.z + p0.w))
                          + ((p1.x + p1.y) + (p1.z + p1.w))
                          + xp_pre + sm_bias[tid >> 3];
        }
        __syncthreads();

        if (tid < 64) {
            int j = jb + ejl;
            float gi = sm_gates[(0 * 8 + ejl) * 8 + eb];
            float gf = sm_gates[(1 * 8 + ejl) * 8 + eb];
            float gg = sm_gates[(2 * 8 + ejl) * 8 + eb];
            float go = sm_gates[(3 * 8 + ejl) * 8 + eb];
            gi = 1.f / (1.f + expf(-gi));
            gf = 1.f / (1.f + expf(-gf));
            gg = tanhf(gg);
            go = 1.f / (1.f + expf(-go));
            c_reg = gf * c_reg + gi * gg;
            float h = go * tanhf(c_reg);
            hnext[eb * HID + j] = h;
            size_t di = ((size_t)eb * TT + t) * HID + j;
            float hh = __bfloat162float(__float2bfloat16(h));
            g_hh2[di] = __float2bfloat16(h);
            g_hl2[di] = __float2bfloat16(h - hh);
            if (t == TT - 1) g_c[eb * HID + j] = c_reg;
        }

        // flat all-poll grid barrier
        __syncthreads();
        __threadfence();
        if (tid == 0)
            *(volatile int*)&g_bar_flags[blockIdx.x * 32] = t + 1;
        if (wid == 0) {
            int idx = lane * 4;
            for (;;) {
                int ok = 1;
                #pragma unroll
                for (int q = 0; q < 4; q++)
                    ok &= (*(volatile int*)&g_bar_flags[(idx + q) * 32] >= t + 1);
                if (__all_sync(0xffffffffu, ok)) break;
            }
        }
        __syncthreads();
    }
}

// ---------------- LSE partial reduce + subtract ----------------
__global__ void __launch_bounds__(256)
lse_reduce_kernel(const float2* __restrict__ part)
{
    int row = blockIdx.x * 8 + (threadIdx.x >> 5);
    int lane = threadIdx.x & 31;
    float m = -1e30f, s = 0.f;
    for (int i = lane; i < NPART; i += 32) {
        float2 p = part[(size_t)row * NPART + i];
        float mm = fmaxf(m, p.x);
        s = s * fexp(m - mm) + p.y * fexp(p.x - mm);
        m = mm;
    }
    #pragma unroll
    for (int off = 16; off; off >>= 1) {
        float m2 = __shfl_xor_sync(0xffffffffu, m, off);
        float s2 = __shfl_xor_sync(0xffffffffu, s, off);
        float mm = fmaxf(m, m2);
        s = s * fexp(m - mm) + s2 * fexp(m2 - mm);
        m = mm;
    }
    if (lane == 0) g_lse[row] = m + logf(s);
}

__global__ void __launch_bounds__(256)
sub_lse_kernel(float* __restrict__ out)
{
    int row = blockIdx.x;
    float l = g_lse[row];
    float* p = out + (size_t)row * VOC;
    int head = (int)(((16 - ((uintptr_t)p & 15)) & 15) >> 2);
    if (head > VOC) head = VOC;
    if (threadIdx.x < head) p[threadIdx.x] -= l;
    int n4 = (VOC - head) >> 2;
    float4* p4 = (float4*)(p + head);
    for (int i = threadIdx.x; i < n4; i += 256) {
        float4 v = p4[i];
        v.x -= l; v.y -= l; v.z -= l; v.w -= l;
        p4[i] = v;
    }
    int tail = head + n4 * 4;
    int rem = VOC - tail;
    if ((int)threadIdx.x < rem) p[tail + threadIdx.x] -= l;
}

__global__ void write_hidden_kernel(float* __restrict__ out)
{
    int i = blockIdx.x * blockDim.x + threadIdx.x;
    size_t base = (size_t)MM * VOC;
    if (i < BB * HID)               out[base + i] = g_hbuf[0][i];
    else if (i < 2 * BB * HID)      out[base + i] = g_c[i - BB * HID];
}

// ---------------- launcher ----------------
extern "C" void kernel_launch(void* const* d_in, const int* in_sizes, int n_in,
                              void* d_out, int out_size)
{
    const int*   x     = (const int*)  d_in[0];
    const float* emb_W = (const float*)d_in[1];
    const float* w_ih  = (const float*)d_in[2];
    const float* w_hh  = (const float*)d_in[3];
    const float* b_ih  = (const float*)d_in[4];
    const float* b_hh  = (const float*)d_in[5];
    const float* dec_b = (const float*)d_in[6];
    float* out = (float*)d_out;

    float* xproj_p; cudaGetSymbolAddress((void**)&xproj_p, g_xproj);
    float2* lsepart_p; cudaGetSymbolAddress((void**)&lsepart_p, g_lsepart);
    __nv_bfloat16 *ebh, *ebl, *wh, *wl, *rwh, *rwl, *xh, *xl, *hh2, *hl2;
    cudaGetSymbolAddress((void**)&ebh, g_ebh);
    cudaGetSymbolAddress((void**)&ebl, g_ebl);
    cudaGetSymbolAddress((void**)&wh,  g_wh);
    cudaGetSymbolAddress((void**)&wl,  g_wl);
    cudaGetSymbolAddress((void**)&rwh, g_rwh);
    cudaGetSymbolAddress((void**)&rwl, g_rwl);
    cudaGetSymbolAddress((void**)&xh,  g_xh);
    cudaGetSymbolAddress((void**)&xl,  g_xl);
    cudaGetSymbolAddress((void**)&hh2, g_hh2);
    cudaGetSymbolAddress((void**)&hl2, g_hl2);

    cudaFuncSetAttribute(lstm_persistent_kernel,
                         cudaFuncAttributeMaxDynamicSharedMemorySize, LP_SMEM);
    cudaFuncSetAttribute(mm_bf16_kernel,
                         cudaFuncAttributeMaxDynamicSharedMemorySize, MMSMEM);

    // (1) gather + state-zero fused
    gather_kernel<<<MM, 128>>>(x, emb_W, xh, xl);

    // (2)(3) weight splits (bigger grids for occupancy)
    split_kernel<<<1024, 256>>>(w_ih, wh,  wl,  (long)GATES * HID / 8);
    split_kernel<<<1024, 256>>>(w_hh, rwh, rwl, (long)GATES * HID / 8);

    // (4) x_proj TRANSPOSED: C[gate][m] = w_ih @ emb^T (bias folded into LSTM)
    {
        dim3 grid(GATES / 128, MM / 128);
        mm_bf16_kernel<<<grid, 256, MMSMEM>>>(wh, wl, xh, xl,
                                              (const float*)0, (const float*)0,
                                              xproj_p, MM, MM, HID, (float2*)0);
    }

    // (5) LSTM — now the 5th launch so ncu (-s 5 -c 1) profiles it
    lstm_persistent_kernel<<<HID / 8, 256, LP_SMEM>>>(rwh, rwl, b_ih, b_hh);

    // (6) decoder-weight split (only needed by the decoder)
    split_kernel<<<4096, 256>>>(emb_W, ebh, ebl, (long)VOC * HID / 8);

    // (7) decoder: logits = h_all @ emb_W^T + dec_b, with fused LSE partials
    {
        dim3 grid(MM / 128, NPART);
        mm_bf16_kernel<<<grid, 256, MMSMEM>>>(hh2, hl2, ebh, ebl, dec_b,
                                              (const float*)0, out, VOC, VOC, HID,
                                              lsepart_p);
    }

    // (8)(9) log-softmax
    lse_reduce_kernel<<<MM / 8, 256>>>(lsepart_p);
    sub_lse_kernel<<<MM, 256>>>(out);

    // (10) optional hidden-state tail
    if (out_size >= MM * VOC + 2 * BB * HID)
        write_hidden_kernel<<<(2 * BB * HID + 255) / 256, 256>>>(out);
}